// round 3
// baseline (speedup 1.0000x reference)
#include <cuda_runtime.h>
#include <math.h>

#define B_    8
#define LQ_   2048
#define LK_   1024
#define QIN   1124
#define KIN   10100
#define PROJ_ 500
#define HEADS 10
#define HD    50

typedef unsigned long long u64;

// packed fp32x2 FMA: d = a*b + d (elementwise on the two lanes)
__device__ __forceinline__ void ffma2(u64 &d, u64 a, u64 b) {
    asm("fma.rn.f32x2 %0, %1, %2, %0;" : "+l"(d) : "l"(a), "l"(b));
}
__device__ __forceinline__ float lane_sum(u64 v) {
    return __uint_as_float((unsigned)(v & 0xffffffffull)) +
           __uint_as_float((unsigned)(v >> 32));
}

// Scratch (allocation-free)
__device__ float g_q[B_ * LQ_ * PROJ_];      // 16384 x 500
__device__ float g_k[B_ * LK_ * PROJ_];      // 8192  x 500
__device__ float g_attn[B_ * LQ_ * HEADS];   // 16384 x 10

// ---------------------------------------------------------------------------
// SGEMM v3 (FFMA2): C[M,N] = A[M,K] @ W[K,N] + bias[N]
// 128x64 tile, BK=16 stored as 8 k-pairs (float2), double-buffered.
// 256 threads, per-thread 8m x 4n outputs, packed accumulation along k.
// ---------------------------------------------------------------------------
#define BM 128
#define BN 64
#define BK 16

__global__ __launch_bounds__(256, 2) void sgemm_bias(
    const float* __restrict__ A, const float* __restrict__ W,
    const float* __restrict__ bias, float* __restrict__ C,
    int M, int N, int K)
{
    __shared__ float2 As2[2][8][BM + 4];   // [buf][kk2][m] = (A[k],A[k+1])
    __shared__ float2 Bs2[2][8][BN + 2];   // [buf][kk2][n] = (W[k],W[k+1])

    const int t  = threadIdx.x;
    const int tx = t & 15;
    const int ty = t >> 4;
    const int m0 = blockIdx.y * BM;
    const int n0 = blockIdx.x * BN;

    // A fetch: 512 float4 (128 rows x 4 f4); this thread: rows ar0, ar0+64
    const int ar0 = t >> 2;
    const int ac  = (t & 3) * 4;      // k offset within tile: 0,4,8,12
    const int ac2 = ac >> 1;          // k-pair row in As2
    const int ar1 = ar0 + 64;
    // B fetch: threads t<128: k-pair row bk2, 4 n's
    const int  bk2     = t >> 4;      // 0..7 (t<128)
    const int  bnc     = (t & 15) * 4;
    const bool bactive = (t < 128);

    float4 ra0, ra1, rb0, rb1;

    auto load_a = [&](int k0, int r) -> float4 {
        float4 v = make_float4(0.f, 0.f, 0.f, 0.f);
        int rem = K - (k0 + ac);
        const float* p = &A[(size_t)(m0 + r) * K + k0 + ac];
        if (rem >= 4) return *(const float4*)p;
        if (rem >= 1) v.x = p[0];
        if (rem >= 2) v.y = p[1];
        if (rem >= 3) v.z = p[2];
        return v;
    };
    auto load_b_row = [&](int k) -> float4 {
        float4 v = make_float4(0.f, 0.f, 0.f, 0.f);
        if (k < K) {
            const float* p = &W[(size_t)k * N + n0 + bnc];
            if (n0 + bnc + 3 < N) return *(const float4*)p;
            if (n0 + bnc     < N) v.x = p[0];
            if (n0 + bnc + 1 < N) v.y = p[1];
            if (n0 + bnc + 2 < N) v.z = p[2];
        }
        return v;
    };
    auto fetch = [&](int k0) {
        ra0 = load_a(k0, ar0);
        ra1 = load_a(k0, ar1);
        if (bactive) {
            rb0 = load_b_row(k0 + 2 * bk2);
            rb1 = load_b_row(k0 + 2 * bk2 + 1);
        }
    };
    auto stage = [&](int buf) {
        As2[buf][ac2    ][ar0] = make_float2(ra0.x, ra0.y);
        As2[buf][ac2 + 1][ar0] = make_float2(ra0.z, ra0.w);
        As2[buf][ac2    ][ar1] = make_float2(ra1.x, ra1.y);
        As2[buf][ac2 + 1][ar1] = make_float2(ra1.z, ra1.w);
        if (bactive) {
            const float* p0 = (const float*)&rb0;
            const float* p1 = (const float*)&rb1;
#pragma unroll
            for (int i = 0; i < 4; i++)
                Bs2[buf][bk2][bnc + i] = make_float2(p0[i], p1[i]);
        }
    };

    u64 acc2[8][4];
#pragma unroll
    for (int i = 0; i < 8; i++)
#pragma unroll
        for (int j = 0; j < 4; j++) acc2[i][j] = 0ull;

    const int ntiles = (K + BK - 1) / BK;

    fetch(0);
    stage(0);
    __syncthreads();

    for (int tl = 0; tl < ntiles; ++tl) {
        const int cur = tl & 1;
        if (tl + 1 < ntiles) fetch((tl + 1) * BK);

#pragma unroll
        for (int kk2 = 0; kk2 < 8; kk2++) {
            u64 a2[8];
#pragma unroll
            for (int i2 = 0; i2 < 4; i2++) {
                ulonglong2 v = *(const ulonglong2*)&As2[cur][kk2][ty * 8 + 2 * i2];
                a2[2 * i2    ] = v.x;
                a2[2 * i2 + 1] = v.y;
            }
            u64 b2[4];
#pragma unroll
            for (int j = 0; j < 4; j++)
                b2[j] = *(const u64*)&Bs2[cur][kk2][tx + 16 * j];
#pragma unroll
            for (int i = 0; i < 8; i++)
#pragma unroll
                for (int j = 0; j < 4; j++) ffma2(acc2[i][j], a2[i], b2[j]);
        }

        if (tl + 1 < ntiles) stage(cur ^ 1);
        __syncthreads();
    }

#pragma unroll
    for (int i = 0; i < 8; i++) {
        int m = m0 + ty * 8 + i;
#pragma unroll
        for (int j = 0; j < 4; j++) {
            int n = n0 + tx + 16 * j;
            if (n < N) C[(size_t)m * N + n] = lane_sum(acc2[i][j]) + bias[n];
        }
    }
}

// ---------------------------------------------------------------------------
// Fused attention with FFMA2 packed-d score accumulation.
// Per block (b, h, 128-q tile); k streamed in 128-row tiles.
// 8q x 8k frag split into two 4-col passes (register pressure).
// ---------------------------------------------------------------------------
__global__ __launch_bounds__(256, 2) void attn_kernel(const float* __restrict__ value)
{
    extern __shared__ float sm[];
    float* qs  = sm;            // 128*50
    float* ks  = sm + 6400;     // 128*50
    float* vsh = sm + 12800;    // 128

    const int b  = blockIdx.z;
    const int h  = blockIdx.y;
    const int q0 = blockIdx.x * 128;
    const int t  = threadIdx.x;
    const int tx = t & 15;
    const int ty = t >> 4;

    for (int idx = t; idx < 128 * HD; idx += 256) {
        int r = idx / HD;
        int c = idx - r * HD;
        qs[idx] = g_q[(size_t)(b * LQ_ + q0 + r) * PROJ_ + h * HD + c];
    }

    float accA[8], accL[8];
#pragma unroll
    for (int i = 0; i < 8; i++) { accA[i] = 0.0f; accL[i] = 0.0f; }

    const float scale = 0.14142135623730951f; // 1/sqrt(50)

    for (int kt = 0; kt < LK_; kt += 128) {
        __syncthreads();
        for (int idx = t; idx < 128 * HD; idx += 256) {
            int r = idx / HD;
            int c = idx - r * HD;
            ks[idx] = g_k[(size_t)(b * LK_ + kt + r) * PROJ_ + h * HD + c];
        }
        if (t < 128) vsh[t] = value[b * LK_ + kt + t];
        __syncthreads();

#pragma unroll
        for (int jh = 0; jh < 2; jh++) {
            u64 s2[8][4];
#pragma unroll
            for (int i = 0; i < 8; i++)
#pragma unroll
                for (int j = 0; j < 4; j++) s2[i][j] = 0ull;

#pragma unroll
            for (int d2 = 0; d2 < HD / 2; d2++) {
                u64 a2[8], b2[4];
#pragma unroll
                for (int i = 0; i < 8; i++)
                    a2[i] = *(const u64*)&qs[(ty * 8 + i) * HD + 2 * d2];
#pragma unroll
                for (int j = 0; j < 4; j++)
                    b2[j] = *(const u64*)&ks[(tx + 16 * (jh * 4 + j)) * HD + 2 * d2];
#pragma unroll
                for (int i = 0; i < 8; i++)
#pragma unroll
                    for (int j = 0; j < 4; j++) ffma2(s2[i][j], a2[i], b2[j]);
            }

#pragma unroll
            for (int j = 0; j < 4; j++) {
                float v = vsh[tx + 16 * (jh * 4 + j)];
#pragma unroll
                for (int i = 0; i < 8; i++) {
                    float e = __expf(lane_sum(s2[i][j]) * scale);
                    accA[i] += e * v;
                    accL[i] += e;
                }
            }
        }
    }

#pragma unroll
    for (int i = 0; i < 8; i++) {
        float a = accA[i];
        float l = accL[i];
#pragma unroll
        for (int o = 8; o > 0; o >>= 1) {
            a += __shfl_xor_sync(0xffffffffu, a, o);
            l += __shfl_xor_sync(0xffffffffu, l, o);
        }
        if (tx == 0)
            g_attn[(size_t)(b * LQ_ + q0 + ty * 8 + i) * HEADS + h] = a / l;
    }
}

// ---------------------------------------------------------------------------
// Tiny MLP: y = relu(relu(o @ W1 + b1) @ W2 + b2)
// ---------------------------------------------------------------------------
__global__ __launch_bounds__(256) void mlp_kernel(
    const float* __restrict__ W1, const float* __restrict__ b1,
    const float* __restrict__ W2, const float* __restrict__ b2,
    float* __restrict__ out)
{
    int idx = blockIdx.x * blockDim.x + threadIdx.x;
    if (idx >= B_ * LQ_) return;

    float o[HEADS];
#pragma unroll
    for (int i = 0; i < HEADS; i++) o[i] = g_attn[(size_t)idx * HEADS + i];

    float y = b2[0];
#pragma unroll
    for (int j = 0; j < 10; j++) {
        float hj = b1[j];
#pragma unroll
        for (int i = 0; i < HEADS; i++) hj += o[i] * W1[i * 10 + j];
        hj = fmaxf(hj, 0.0f);
        y += hj * W2[j];
    }
    out[idx] = fmaxf(y, 0.0f);
}

// ---------------------------------------------------------------------------
extern "C" void kernel_launch(void* const* d_in, const int* in_sizes, int n_in,
                              void* d_out, int out_size)
{
    const float* query = (const float*)d_in[0];
    const float* key   = (const float*)d_in[1];
    const float* value = (const float*)d_in[2];
    const float* Wq    = (const float*)d_in[3];
    const float* bq    = (const float*)d_in[4];
    const float* Wk    = (const float*)d_in[5];
    const float* bk    = (const float*)d_in[6];
    const float* W1    = (const float*)d_in[7];
    const float* b1    = (const float*)d_in[8];
    const float* W2    = (const float*)d_in[9];
    const float* b2    = (const float*)d_in[10];
    float* out = (float*)d_out;

    float *gq = nullptr, *gk = nullptr;
    cudaGetSymbolAddress((void**)&gq, g_q);
    cudaGetSymbolAddress((void**)&gk, g_k);

    // q projection: [16384,1124] @ [1124,500]
    {
        dim3 grid((PROJ_ + BN - 1) / BN, (B_ * LQ_) / BM);
        sgemm_bias<<<grid, 256>>>(query, Wq, bq, gq, B_ * LQ_, PROJ_, QIN);
    }
    // k projection: [8192,10100] @ [10100,500]
    {
        dim3 grid((PROJ_ + BN - 1) / BN, (B_ * LK_) / BM);
        sgemm_bias<<<grid, 256>>>(key, Wk, bk, gk, B_ * LK_, PROJ_, KIN);
    }
    // fused attention
    {
        const int smem = (128 * HD + 128 * HD + 128) * (int)sizeof(float); // 51,712 B
        cudaFuncSetAttribute(attn_kernel,
                             cudaFuncAttributeMaxDynamicSharedMemorySize, smem);
        dim3 grid(LQ_ / 128, HEADS, B_);
        attn_kernel<<<grid, 256, smem>>>(value);
    }
    // MLP head
    {
        int n = B_ * LQ_;
        mlp_kernel<<<(n + 255) / 256, 256>>>(W1, b1, W2, b2, out);
    }
}

// round 4
// speedup vs baseline: 2.6762x; 2.6762x over previous
#include <cuda_runtime.h>
#include <cuda_bf16.h>
#include <math.h>

#define B_    8
#define LQ_   2048
#define LK_   1024
#define QIN   1124
#define KIN   10100
#define PROJ_ 500
#define HEADS 10
#define HD    50

#define KPQ   1152   // QIN padded to mult of 32
#define KPK   10112  // KIN padded to mult of 32
#define NP    512    // PROJ padded

typedef unsigned int u32;

// ---------------- scratch (allocation-free) ----------------
__device__ float g_q[B_ * LQ_ * PROJ_];
__device__ float g_k[B_ * LK_ * PROJ_];
__device__ float g_attn[B_ * LQ_ * HEADS];

__device__ __nv_bfloat16 g_qh[B_ * LQ_ * KPQ];
__device__ __nv_bfloat16 g_ql[B_ * LQ_ * KPQ];
__device__ __nv_bfloat16 g_kh[B_ * LK_ * KPK];
__device__ __nv_bfloat16 g_kl[B_ * LK_ * KPK];
__device__ __nv_bfloat16 g_wqh[KPQ * NP];
__device__ __nv_bfloat16 g_wql[KPQ * NP];
__device__ __nv_bfloat16 g_wkh[KPK * NP];
__device__ __nv_bfloat16 g_wkl[KPK * NP];

// ---------------- fp32 -> (hi, lo) bf16 split with padding ----------------
// grid.x = padded rows; pads cols [cols, colsp) and rows [rows, gridDim.x) with 0
__global__ void split_bf16(const float* __restrict__ X,
                           __nv_bfloat16* __restrict__ H,
                           __nv_bfloat16* __restrict__ L,
                           int rows, int cols, int colsp)
{
    int r = blockIdx.x;
    bool rv = (r < rows);
    for (int c = threadIdx.x; c < colsp; c += blockDim.x) {
        float x = (rv && c < cols) ? X[(size_t)r * cols + c] : 0.0f;
        __nv_bfloat16 h = __float2bfloat16(x);
        size_t o = (size_t)r * colsp + c;
        H[o] = h;
        L[o] = __float2bfloat16(x - __bfloat162float(h));
    }
}

// ---------------- mma / ldmatrix helpers ----------------
__device__ __forceinline__ void ldsm_x4(u32* r, u32 addr) {
    asm volatile("ldmatrix.sync.aligned.m8n8.x4.shared.b16 {%0,%1,%2,%3}, [%4];"
        : "=r"(r[0]), "=r"(r[1]), "=r"(r[2]), "=r"(r[3]) : "r"(addr));
}
__device__ __forceinline__ void ldsm_x4_t(u32* r, u32 addr) {
    asm volatile("ldmatrix.sync.aligned.m8n8.x4.trans.shared.b16 {%0,%1,%2,%3}, [%4];"
        : "=r"(r[0]), "=r"(r[1]), "=r"(r[2]), "=r"(r[3]) : "r"(addr));
}
__device__ __forceinline__ void mma_bf16(float* d, const u32* a, const u32* b) {
    asm volatile(
        "mma.sync.aligned.m16n8k16.row.col.f32.bf16.bf16.f32 "
        "{%0,%1,%2,%3},{%4,%5,%6,%7},{%8,%9},{%0,%1,%2,%3};"
        : "+f"(d[0]), "+f"(d[1]), "+f"(d[2]), "+f"(d[3])
        : "r"(a[0]), "r"(a[1]), "r"(a[2]), "r"(a[3]), "r"(b[0]), "r"(b[1]));
}

// ---------------- bf16x3 GEMM: C = Ah*Wh + Ah*Wl + Al*Wh + bias ----------------
// CTA tile 128x64, BK=32 (bf16), 8 warps (4m x 2n), warp tile 32x32.
// A: [M][Kp] row-major (hi/lo), W: [Kp][NP] row-major (hi/lo), all zero-padded.
#define BM  128
#define BN  64
#define BKB 32
#define AST 40            // smem row stride (bf16) for A tiles
#define WST 72            // smem row stride (bf16) for W tiles
#define A_BUF (BM * AST)  // 5120 bf16 per buffer
#define W_BUF (BKB * WST) // 2304 bf16 per buffer
#define GEMM_SMEM ((4 * A_BUF + 4 * W_BUF) * 2) // bytes = 59392

__global__ __launch_bounds__(256, 2) void gemm_bf16x3(
    const __nv_bfloat16* __restrict__ Ah, const __nv_bfloat16* __restrict__ Al,
    const __nv_bfloat16* __restrict__ Wh, const __nv_bfloat16* __restrict__ Wl,
    const float* __restrict__ bias, float* __restrict__ C,
    int M, int N, int Kp)
{
    extern __shared__ __nv_bfloat16 sm[];
    __nv_bfloat16* sAh = sm;
    __nv_bfloat16* sAl = sm + 2 * A_BUF;
    __nv_bfloat16* sWh = sm + 4 * A_BUF;
    __nv_bfloat16* sWl = sm + 4 * A_BUF + 2 * W_BUF;

    const int t    = threadIdx.x;
    const int lane = t & 31;
    const int warp = t >> 5;
    const int wm   = warp >> 1;   // 0..3 -> 32 m-rows each
    const int wn   = warp & 1;    // 0..1 -> 32 n-cols each
    const int m0   = blockIdx.y * BM;
    const int n0   = blockIdx.x * BN;

    // A staging: 1024 uint2 per matrix (128 rows x 8 uint2); thread does i=0..3
    const int ar = t >> 3;        // base row (advance +32 per i)
    const int ac = t & 7;         // uint2 col (4 bf16 each)
    // W staging: 512 uint2 per matrix (32 rows x 16 uint2); thread does i=0..1
    const int wr = t >> 4;        // base row (advance +16 per i)
    const int wc = t & 15;

    uint2 rAh[4], rAl[4], rWh[2], rWl[2];

    auto fetch = [&](int k0) {
#pragma unroll
        for (int i = 0; i < 4; i++) {
            size_t off = (size_t)(m0 + ar + i * 32) * Kp + k0 + ac * 4;
            rAh[i] = *(const uint2*)(Ah + off);
            rAl[i] = *(const uint2*)(Al + off);
        }
#pragma unroll
        for (int i = 0; i < 2; i++) {
            size_t off = (size_t)(k0 + wr + i * 16) * NP + n0 + wc * 4;
            rWh[i] = *(const uint2*)(Wh + off);
            rWl[i] = *(const uint2*)(Wl + off);
        }
    };
    auto stage = [&](int buf) {
#pragma unroll
        for (int i = 0; i < 4; i++) {
            int off = buf * A_BUF + (ar + i * 32) * AST + ac * 4;
            *(uint2*)(sAh + off) = rAh[i];
            *(uint2*)(sAl + off) = rAl[i];
        }
#pragma unroll
        for (int i = 0; i < 2; i++) {
            int off = buf * W_BUF + (wr + i * 16) * WST + wc * 4;
            *(uint2*)(sWh + off) = rWh[i];
            *(uint2*)(sWl + off) = rWl[i];
        }
    };

    float acc[2][4][4];
#pragma unroll
    for (int mt = 0; mt < 2; mt++)
#pragma unroll
        for (int nt = 0; nt < 4; nt++)
#pragma unroll
            for (int e = 0; e < 4; e++) acc[mt][nt][e] = 0.0f;

    const int lrow = lane & 15;
    const int lcol = lane >> 4;
    const int ntiles = Kp / BKB;

    fetch(0);
    stage(0);
    __syncthreads();

    for (int tl = 0; tl < ntiles; ++tl) {
        const int cur = tl & 1;
        if (tl + 1 < ntiles) fetch((tl + 1) * BKB);

        u32 bAh = (u32)__cvta_generic_to_shared(sAh + cur * A_BUF);
        u32 bAl = (u32)__cvta_generic_to_shared(sAl + cur * A_BUF);
        u32 bWh = (u32)__cvta_generic_to_shared(sWh + cur * W_BUF);
        u32 bWl = (u32)__cvta_generic_to_shared(sWl + cur * W_BUF);

#pragma unroll
        for (int kk = 0; kk < 2; kk++) {
            u32 aH[2][4], aL[2][4], bH[8], bL[8];
#pragma unroll
            for (int mt = 0; mt < 2; mt++) {
                u32 off = ((wm * 32 + mt * 16 + lrow) * AST + kk * 16 + lcol * 8) * 2;
                ldsm_x4(aH[mt], bAh + off);
                ldsm_x4(aL[mt], bAl + off);
            }
#pragma unroll
            for (int hf = 0; hf < 2; hf++) {
                u32 off = ((kk * 16 + lrow) * WST + wn * 32 + hf * 16 + lcol * 8) * 2;
                ldsm_x4_t(bH + hf * 4, bWh + off);
                ldsm_x4_t(bL + hf * 4, bWl + off);
            }
#pragma unroll
            for (int mt = 0; mt < 2; mt++)
#pragma unroll
                for (int nt = 0; nt < 4; nt++) {
                    mma_bf16(acc[mt][nt], aH[mt], &bH[nt * 2]);
                    mma_bf16(acc[mt][nt], aH[mt], &bL[nt * 2]);
                    mma_bf16(acc[mt][nt], aL[mt], &bH[nt * 2]);
                }
        }

        if (tl + 1 < ntiles) stage(cur ^ 1);
        __syncthreads();
    }

    // epilogue: m16n8 accum mapping: d0/d1 row=lane>>2 cols 2*(lane&3)(+1); d2/d3 row+8
#pragma unroll
    for (int mt = 0; mt < 2; mt++) {
#pragma unroll
        for (int nt = 0; nt < 4; nt++) {
            int row = wm * 32 + mt * 16 + (lane >> 2);
            int col = wn * 32 + nt * 8 + (lane & 3) * 2;
            int m = m0 + row;
            int n = n0 + col;
            if (n < N)     C[(size_t)m * N + n]         = acc[mt][nt][0] + bias[n];
            if (n + 1 < N) C[(size_t)m * N + n + 1]     = acc[mt][nt][1] + bias[n + 1];
            if (n < N)     C[(size_t)(m + 8) * N + n]     = acc[mt][nt][2] + bias[n];
            if (n + 1 < N) C[(size_t)(m + 8) * N + n + 1] = acc[mt][nt][3] + bias[n + 1];
        }
    }
}

// ---------------- fused attention (R2 proven version, fp32) ----------------
__global__ __launch_bounds__(256) void attn_kernel(const float* __restrict__ value)
{
    extern __shared__ float smf[];
    float* qs  = smf;
    float* ks  = smf + 6400;
    float* vsh = smf + 12800;

    const int b  = blockIdx.z;
    const int h  = blockIdx.y;
    const int q0 = blockIdx.x * 128;
    const int t  = threadIdx.x;
    const int tx = t & 15;
    const int ty = t >> 4;

    for (int idx = t; idx < 128 * HD; idx += 256) {
        int r = idx / HD;
        int c = idx - r * HD;
        qs[idx] = g_q[(size_t)(b * LQ_ + q0 + r) * PROJ_ + h * HD + c];
    }

    float accA[8], accL[8];
#pragma unroll
    for (int i = 0; i < 8; i++) { accA[i] = 0.0f; accL[i] = 0.0f; }

    const float scale = 0.14142135623730951f;

    for (int kt = 0; kt < LK_; kt += 128) {
        __syncthreads();
        for (int idx = t; idx < 128 * HD; idx += 256) {
            int r = idx / HD;
            int c = idx - r * HD;
            ks[idx] = g_k[(size_t)(b * LK_ + kt + r) * PROJ_ + h * HD + c];
        }
        if (t < 128) vsh[t] = value[b * LK_ + kt + t];
        __syncthreads();

        float s[8][8];
#pragma unroll
        for (int i = 0; i < 8; i++)
#pragma unroll
            for (int j = 0; j < 8; j++) s[i][j] = 0.0f;

#pragma unroll
        for (int d = 0; d < HD; d += 2) {
            float2 a[8], bb[8];
#pragma unroll
            for (int i = 0; i < 8; i++)
                a[i] = *(const float2*)&qs[(ty * 8 + i) * HD + d];
#pragma unroll
            for (int j = 0; j < 8; j++)
                bb[j] = *(const float2*)&ks[(tx + 16 * j) * HD + d];
#pragma unroll
            for (int i = 0; i < 8; i++)
#pragma unroll
                for (int j = 0; j < 8; j++) {
                    s[i][j] += a[i].x * bb[j].x;
                    s[i][j] += a[i].y * bb[j].y;
                }
        }

#pragma unroll
        for (int j = 0; j < 8; j++) {
            float v = vsh[tx + 16 * j];
#pragma unroll
            for (int i = 0; i < 8; i++) {
                float e = __expf(s[i][j] * scale);
                accA[i] += e * v;
                accL[i] += e;
            }
        }
    }

#pragma unroll
    for (int i = 0; i < 8; i++) {
        float a = accA[i];
        float l = accL[i];
#pragma unroll
        for (int o = 8; o > 0; o >>= 1) {
            a += __shfl_xor_sync(0xffffffffu, a, o);
            l += __shfl_xor_sync(0xffffffffu, l, o);
        }
        if (tx == 0)
            g_attn[(size_t)(b * LQ_ + q0 + ty * 8 + i) * HEADS + h] = a / l;
    }
}

// ---------------- tiny MLP ----------------
__global__ __launch_bounds__(256) void mlp_kernel(
    const float* __restrict__ W1, const float* __restrict__ b1,
    const float* __restrict__ W2, const float* __restrict__ b2,
    float* __restrict__ out)
{
    int idx = blockIdx.x * blockDim.x + threadIdx.x;
    if (idx >= B_ * LQ_) return;

    float o[HEADS];
#pragma unroll
    for (int i = 0; i < HEADS; i++) o[i] = g_attn[(size_t)idx * HEADS + i];

    float y = b2[0];
#pragma unroll
    for (int j = 0; j < 10; j++) {
        float hj = b1[j];
#pragma unroll
        for (int i = 0; i < HEADS; i++) hj += o[i] * W1[i * 10 + j];
        hj = fmaxf(hj, 0.0f);
        y += hj * W2[j];
    }
    out[idx] = fmaxf(y, 0.0f);
}

// ---------------------------------------------------------------------------
extern "C" void kernel_launch(void* const* d_in, const int* in_sizes, int n_in,
                              void* d_out, int out_size)
{
    const float* query = (const float*)d_in[0];
    const float* key   = (const float*)d_in[1];
    const float* value = (const float*)d_in[2];
    const float* Wq    = (const float*)d_in[3];
    const float* bq    = (const float*)d_in[4];
    const float* Wk    = (const float*)d_in[5];
    const float* bk    = (const float*)d_in[6];
    const float* W1    = (const float*)d_in[7];
    const float* b1    = (const float*)d_in[8];
    const float* W2    = (const float*)d_in[9];
    const float* b2    = (const float*)d_in[10];
    float* out = (float*)d_out;

    float *gq, *gk;
    __nv_bfloat16 *qh, *ql, *kh, *kl, *wqh, *wql, *wkh, *wkl;
    cudaGetSymbolAddress((void**)&gq,  g_q);
    cudaGetSymbolAddress((void**)&gk,  g_k);
    cudaGetSymbolAddress((void**)&qh,  g_qh);
    cudaGetSymbolAddress((void**)&ql,  g_ql);
    cudaGetSymbolAddress((void**)&kh,  g_kh);
    cudaGetSymbolAddress((void**)&kl,  g_kl);
    cudaGetSymbolAddress((void**)&wqh, g_wqh);
    cudaGetSymbolAddress((void**)&wql, g_wql);
    cudaGetSymbolAddress((void**)&wkh, g_wkh);
    cudaGetSymbolAddress((void**)&wkl, g_wkl);

    // conversions (padded, zero-filled)
    split_bf16<<<B_ * LQ_, 256>>>(query, qh, ql, B_ * LQ_, QIN, KPQ);
    split_bf16<<<B_ * LK_, 256>>>(key,   kh, kl, B_ * LK_, KIN, KPK);
    split_bf16<<<KPQ,      256>>>(Wq,  wqh, wql, QIN, PROJ_, NP);
    split_bf16<<<KPK,      256>>>(Wk,  wkh, wkl, KIN, PROJ_, NP);

    cudaFuncSetAttribute(gemm_bf16x3,
                         cudaFuncAttributeMaxDynamicSharedMemorySize, GEMM_SMEM);

    // q projection
    {
        dim3 grid(NP / BN, (B_ * LQ_) / BM);
        gemm_bf16x3<<<grid, 256, GEMM_SMEM>>>(qh, ql, wqh, wql, bq, gq,
                                              B_ * LQ_, PROJ_, KPQ);
    }
    // k projection
    {
        dim3 grid(NP / BN, (B_ * LK_) / BM);
        gemm_bf16x3<<<grid, 256, GEMM_SMEM>>>(kh, kl, wkh, wkl, bk, gk,
                                              B_ * LK_, PROJ_, KPK);
    }
    // fused attention
    {
        const int smem = (128 * HD + 128 * HD + 128) * (int)sizeof(float);
        cudaFuncSetAttribute(attn_kernel,
                             cudaFuncAttributeMaxDynamicSharedMemorySize, smem);
        dim3 grid(LQ_ / 128, HEADS, B_);
        attn_kernel<<<grid, 256, smem>>>(value);
    }
    // MLP head
    {
        int n = B_ * LQ_;
        mlp_kernel<<<(n + 255) / 256, 256>>>(W1, b1, W2, b2, out);
    }
}

// round 7
// speedup vs baseline: 3.5116x; 1.3122x over previous
#include <cuda_runtime.h>
#include <cuda_bf16.h>
#include <math.h>

#define B_    8
#define LQ_   2048
#define LK_   1024
#define QIN   1124
#define KIN   10100
#define PROJ_ 500
#define HEADS 10
#define HD    50

#define KPQ   1152   // QIN padded
#define KPK   10112  // KIN padded
#define NP    512    // PROJ padded
#define HDP   64     // head_dim padded for MMA

typedef unsigned int u32;

// ---------------- scratch (allocation-free; zero-initialized) ----------------
__device__ float g_attn[B_ * LQ_ * HEADS];

__device__ __nv_bfloat16 g_qh[B_ * LQ_ * KPQ];   // split inputs
__device__ __nv_bfloat16 g_ql[B_ * LQ_ * KPQ];
__device__ __nv_bfloat16 g_kh[B_ * LK_ * KPK];
__device__ __nv_bfloat16 g_kl[B_ * LK_ * KPK];
__device__ __nv_bfloat16 g_wqh[KPQ * NP];        // W [Kp][NP] row-major
__device__ __nv_bfloat16 g_wql[KPQ * NP];
__device__ __nv_bfloat16 g_wkh[KPK * NP];
__device__ __nv_bfloat16 g_wkl[KPK * NP];

// projected q/k in attention layout [b, head, seq, HDP], bf16 hi/lo
// pad columns [50,64) are never written -> stay zero (device globals zero-init)
__device__ __nv_bfloat16 g_qah[B_ * HEADS * LQ_ * HDP];
__device__ __nv_bfloat16 g_qal[B_ * HEADS * LQ_ * HDP];
__device__ __nv_bfloat16 g_kah[B_ * HEADS * LK_ * HDP];
__device__ __nv_bfloat16 g_kal[B_ * HEADS * LK_ * HDP];

// ------- fp32 -> (hi,lo) bf16 split (row-major, padded rows AND cols) -------
__global__ void split_bf16(const float* __restrict__ X,
                           __nv_bfloat16* __restrict__ H,
                           __nv_bfloat16* __restrict__ L,
                           int rows, int cols, int colsp)
{
    int r = blockIdx.x;                 // grid.x may exceed rows (pad rows)
    bool rv = (r < rows);
    for (int c = threadIdx.x; c < colsp; c += blockDim.x) {
        float x = (rv && c < cols) ? X[(size_t)r * cols + c] : 0.0f;
        __nv_bfloat16 h = __float2bfloat16(x);
        size_t o = (size_t)r * colsp + c;
        H[o] = h;
        L[o] = __float2bfloat16(x - __bfloat162float(h));
    }
}

// ---------------- mma / ldmatrix helpers ----------------
__device__ __forceinline__ void ldsm_x4(u32* r, u32 addr) {
    asm volatile("ldmatrix.sync.aligned.m8n8.x4.shared.b16 {%0,%1,%2,%3}, [%4];"
        : "=r"(r[0]), "=r"(r[1]), "=r"(r[2]), "=r"(r[3]) : "r"(addr));
}
__device__ __forceinline__ void ldsm_x4_t(u32* r, u32 addr) {
    asm volatile("ldmatrix.sync.aligned.m8n8.x4.trans.shared.b16 {%0,%1,%2,%3}, [%4];"
        : "=r"(r[0]), "=r"(r[1]), "=r"(r[2]), "=r"(r[3]) : "r"(addr));
}
__device__ __forceinline__ void mma_bf16(float* d, const u32* a, const u32* b) {
    asm volatile(
        "mma.sync.aligned.m16n8k16.row.col.f32.bf16.bf16.f32 "
        "{%0,%1,%2,%3},{%4,%5,%6,%7},{%8,%9},{%0,%1,%2,%3};"
        : "+f"(d[0]), "+f"(d[1]), "+f"(d[2]), "+f"(d[3])
        : "r"(a[0]), "r"(a[1]), "r"(a[2]), "r"(a[3]), "r"(b[0]), "r"(b[1]));
}

// ------- bf16x3 GEMM (R4-proven core), epilogue -> attention layout ---------
// A:[M][Kp] hi/lo row-major; W:[Kp][NP] hi/lo row-major (trans ldmatrix).
#define BM  128
#define BN  64
#define BKB 32
#define AST 40
#define WST 72
#define A_BUF (BM * AST)
#define W_BUF (BKB * WST)
#define GEMM_SMEM ((4 * A_BUF + 4 * W_BUF) * 2)

__global__ __launch_bounds__(256, 2) void gemm_bf16x3(
    const __nv_bfloat16* __restrict__ Ah, const __nv_bfloat16* __restrict__ Al,
    const __nv_bfloat16* __restrict__ Wh, const __nv_bfloat16* __restrict__ Wl,
    const float* __restrict__ bias,
    __nv_bfloat16* __restrict__ DH, __nv_bfloat16* __restrict__ DL,
    int Kp, int seqshift)
{
    extern __shared__ __nv_bfloat16 sm[];
    __nv_bfloat16* sAh = sm;
    __nv_bfloat16* sAl = sm + 2 * A_BUF;
    __nv_bfloat16* sWh = sm + 4 * A_BUF;
    __nv_bfloat16* sWl = sm + 4 * A_BUF + 2 * W_BUF;

    const int t    = threadIdx.x;
    const int lane = t & 31;
    const int warp = t >> 5;
    const int wm   = warp >> 1;
    const int wn   = warp & 1;
    const int m0   = blockIdx.y * BM;
    const int n0   = blockIdx.x * BN;

    const int ar = t >> 3;
    const int ac = t & 7;
    const int wr = t >> 4;
    const int wc = t & 15;

    uint2 rAh[4], rAl[4], rWh[2], rWl[2];

    auto fetch = [&](int k0) {
#pragma unroll
        for (int i = 0; i < 4; i++) {
            size_t off = (size_t)(m0 + ar + i * 32) * Kp + k0 + ac * 4;
            rAh[i] = *(const uint2*)(Ah + off);
            rAl[i] = *(const uint2*)(Al + off);
        }
#pragma unroll
        for (int i = 0; i < 2; i++) {
            size_t off = (size_t)(k0 + wr + i * 16) * NP + n0 + wc * 4;
            rWh[i] = *(const uint2*)(Wh + off);
            rWl[i] = *(const uint2*)(Wl + off);
        }
    };
    auto stage = [&](int buf) {
#pragma unroll
        for (int i = 0; i < 4; i++) {
            int off = buf * A_BUF + (ar + i * 32) * AST + ac * 4;
            *(uint2*)(sAh + off) = rAh[i];
            *(uint2*)(sAl + off) = rAl[i];
        }
#pragma unroll
        for (int i = 0; i < 2; i++) {
            int off = buf * W_BUF + (wr + i * 16) * WST + wc * 4;
            *(uint2*)(sWh + off) = rWh[i];
            *(uint2*)(sWl + off) = rWl[i];
        }
    };

    float acc[2][4][4];
#pragma unroll
    for (int mt = 0; mt < 2; mt++)
#pragma unroll
        for (int nt = 0; nt < 4; nt++)
#pragma unroll
            for (int e = 0; e < 4; e++) acc[mt][nt][e] = 0.0f;

    const int lrow = lane & 15;
    const int lcol = lane >> 4;
    const int ntiles = Kp / BKB;

    fetch(0);
    stage(0);
    __syncthreads();

    for (int tl = 0; tl < ntiles; ++tl) {
        const int cur = tl & 1;
        if (tl + 1 < ntiles) fetch((tl + 1) * BKB);

        u32 bAh = (u32)__cvta_generic_to_shared(sAh + cur * A_BUF);
        u32 bAl = (u32)__cvta_generic_to_shared(sAl + cur * A_BUF);
        u32 bWh = (u32)__cvta_generic_to_shared(sWh + cur * W_BUF);
        u32 bWl = (u32)__cvta_generic_to_shared(sWl + cur * W_BUF);

#pragma unroll
        for (int kk = 0; kk < 2; kk++) {
            u32 aH[2][4], aL[2][4], bH[8], bL[8];
#pragma unroll
            for (int mt = 0; mt < 2; mt++) {
                u32 off = ((wm * 32 + mt * 16 + lrow) * AST + kk * 16 + lcol * 8) * 2;
                ldsm_x4(aH[mt], bAh + off);
                ldsm_x4(aL[mt], bAl + off);
            }
#pragma unroll
            for (int hf = 0; hf < 2; hf++) {
                u32 off = ((kk * 16 + lrow) * WST + wn * 32 + hf * 16 + lcol * 8) * 2;
                ldsm_x4_t(bH + hf * 4, bWh + off);
                ldsm_x4_t(bL + hf * 4, bWl + off);
            }
#pragma unroll
            for (int mt = 0; mt < 2; mt++)
#pragma unroll
                for (int nt = 0; nt < 4; nt++) {
                    mma_bf16(acc[mt][nt], aH[mt], &bH[nt * 2]);
                    mma_bf16(acc[mt][nt], aH[mt], &bL[nt * 2]);
                    mma_bf16(acc[mt][nt], aL[mt], &bH[nt * 2]);
                }
        }

        if (tl + 1 < ntiles) stage(cur ^ 1);
        __syncthreads();
    }

    // epilogue: write bf16 hi/lo into [b, head, seq, HDP]
    const int seqlen = 1 << seqshift;
#pragma unroll
    for (int mt = 0; mt < 2; mt++) {
#pragma unroll
        for (int nt = 0; nt < 4; nt++) {
            int row = wm * 32 + mt * 16 + (lane >> 2);
            int col = wn * 32 + nt * 8 + (lane & 3) * 2;
#pragma unroll
            for (int e = 0; e < 4; e++) {
                int m = m0 + row + ((e >> 1) ? 8 : 0);
                int n = n0 + col + (e & 1);
                if (n >= PROJ_) continue;
                int head = n / HD;
                int c    = n - head * HD;
                int bi   = m >> seqshift;
                int si   = m & (seqlen - 1);
                float x = acc[mt][nt][e] + bias[n];
                __nv_bfloat16 h = __float2bfloat16(x);
                size_t o = ((size_t)(bi * HEADS + head) * seqlen + si) * HDP + c;
                DH[o] = h;
                DL[o] = __float2bfloat16(x - __bfloat162float(h));
            }
        }
    }
}

// ---------------- tensor-core attention ----------------
// Block: (b, h, 128-q tile), 8 warps; warp owns 16 q-rows x 128 k-cols.
// S = qh*kh^T + qh*kl^T + ql*kh^T via mma m16n8k16; exp + streaming sums.
// k-columns processed in two 64-col halves to bound register pressure.
#define ATT_ST 72                           // smem row stride (bf16)
#define QH_OFF 0
#define QL_OFF (128 * ATT_ST * 2)           // 18432
#define KH_OFF (2 * QL_OFF)                 // 36864
#define KL_OFF (3 * QL_OFF)                 // 55296
#define V_OFF  (4 * QL_OFF)                 // 73728
#define ATT_SMEM (V_OFF + 128 * 4)          // 74240

__global__ __launch_bounds__(256, 2) void attn_tc(const float* __restrict__ value)
{
    extern __shared__ char smc[];
    const u32 sb = (u32)__cvta_generic_to_shared(smc);
    float* vsh = (float*)(smc + V_OFF);

    const int b  = blockIdx.z;
    const int h  = blockIdx.y;
    const int q0 = blockIdx.x * 128;
    const int t  = threadIdx.x;
    const int lane = t & 31;
    const int w    = t >> 5;

    // stage q tile (128 x 64 bf16, hi+lo)
    {
        const __nv_bfloat16* qh = g_qah + ((size_t)(b * HEADS + h) * LQ_ + q0) * HDP;
        const __nv_bfloat16* ql = g_qal + ((size_t)(b * HEADS + h) * LQ_ + q0) * HDP;
#pragma unroll
        for (int i = 0; i < 4; i++) {
            int idx = t + i * 256;
            int r = idx >> 3, c = idx & 7;
            uint4 vh = *(const uint4*)(qh + (size_t)r * HDP + c * 8);
            uint4 vl = *(const uint4*)(ql + (size_t)r * HDP + c * 8);
            *(uint4*)(smc + QH_OFF + (r * ATT_ST + c * 8) * 2) = vh;
            *(uint4*)(smc + QL_OFF + (r * ATT_ST + c * 8) * 2) = vl;
        }
    }

    float accA[2] = {0.f, 0.f}, accL[2] = {0.f, 0.f};
    const float scale = 0.14142135623730951f;

    // B-operand ldmatrix lane address (non-trans on [n][k] row-major)
    const int bg  = lane >> 3;
    const int bi8 = lane & 7;
    const int brow_off = ((bg & 2) ? 8 : 0) + bi8;
    const int bcol_off = (bg & 1) ? 8 : 0;

    for (int kt = 0; kt < LK_; kt += 128) {
        __syncthreads();
        {
            const __nv_bfloat16* kh = g_kah + ((size_t)(b * HEADS + h) * LK_ + kt) * HDP;
            const __nv_bfloat16* kl = g_kal + ((size_t)(b * HEADS + h) * LK_ + kt) * HDP;
#pragma unroll
            for (int i = 0; i < 4; i++) {
                int idx = t + i * 256;
                int r = idx >> 3, c = idx & 7;
                uint4 vh = *(const uint4*)(kh + (size_t)r * HDP + c * 8);
                uint4 vl = *(const uint4*)(kl + (size_t)r * HDP + c * 8);
                *(uint4*)(smc + KH_OFF + (r * ATT_ST + c * 8) * 2) = vh;
                *(uint4*)(smc + KL_OFF + (r * ATT_ST + c * 8) * 2) = vl;
            }
            if (t < 128) vsh[t] = value[b * LK_ + kt + t];
        }
        __syncthreads();

#pragma unroll
        for (int half = 0; half < 2; half++) {
            float S[8][4];
#pragma unroll
            for (int nt = 0; nt < 8; nt++)
#pragma unroll
                for (int e = 0; e < 4; e++) S[nt][e] = 0.0f;

#pragma unroll
            for (int ks = 0; ks < 4; ks++) {
                const int k0 = ks * 16;
                u32 aH[4], aL[4];
                {
                    u32 off = ((w * 16 + (lane & 15)) * ATT_ST + k0 + (lane >> 4) * 8) * 2;
                    ldsm_x4(aH, sb + QH_OFF + off);
                    ldsm_x4(aL, sb + QL_OFF + off);
                }
#pragma unroll
                for (int ng2 = 0; ng2 < 4; ng2++) {
                    const int ng = half * 4 + ng2;
                    u32 bH[4], bL[4];
                    u32 off = ((ng * 16 + brow_off) * ATT_ST + k0 + bcol_off) * 2;
                    ldsm_x4(bH, sb + KH_OFF + off);
                    ldsm_x4(bL, sb + KL_OFF + off);
                    mma_bf16(S[2 * ng2],     aH, bH);
                    mma_bf16(S[2 * ng2],     aH, bL);
                    mma_bf16(S[2 * ng2],     aL, bH);
                    mma_bf16(S[2 * ng2 + 1], aH, bH + 2);
                    mma_bf16(S[2 * ng2 + 1], aH, bL + 2);
                    mma_bf16(S[2 * ng2 + 1], aL, bH + 2);
                }
            }

            // exp + streaming accumulation for this 64-col half
#pragma unroll
            for (int nt = 0; nt < 8; nt++) {
                int n = (half * 8 + nt) * 8 + (lane & 3) * 2;
                float v0 = vsh[n], v1 = vsh[n + 1];
                float e0 = __expf(S[nt][0] * scale);
                float e1 = __expf(S[nt][1] * scale);
                float e2 = __expf(S[nt][2] * scale);
                float e3 = __expf(S[nt][3] * scale);
                accA[0] += e0 * v0 + e1 * v1;
                accL[0] += e0 + e1;
                accA[1] += e2 * v0 + e3 * v1;
                accL[1] += e2 + e3;
            }
        }
    }

    // reduce across the 4 lanes of each quad (same q-row)
#pragma unroll
    for (int r = 0; r < 2; r++) {
#pragma unroll
        for (int o = 1; o <= 2; o <<= 1) {
            accA[r] += __shfl_xor_sync(0xffffffffu, accA[r], o);
            accL[r] += __shfl_xor_sync(0xffffffffu, accL[r], o);
        }
    }
    if ((lane & 3) == 0) {
        int row = q0 + w * 16 + (lane >> 2);
        g_attn[((size_t)b * LQ_ + row) * HEADS + h]     = accA[0] / accL[0];
        g_attn[((size_t)b * LQ_ + row + 8) * HEADS + h] = accA[1] / accL[1];
    }
}

// ---------------- tiny MLP ----------------
__global__ __launch_bounds__(256) void mlp_kernel(
    const float* __restrict__ W1, const float* __restrict__ b1,
    const float* __restrict__ W2, const float* __restrict__ b2,
    float* __restrict__ out)
{
    int idx = blockIdx.x * blockDim.x + threadIdx.x;
    if (idx >= B_ * LQ_) return;

    float o[HEADS];
#pragma unroll
    for (int i = 0; i < HEADS; i++) o[i] = g_attn[(size_t)idx * HEADS + i];

    float y = b2[0];
#pragma unroll
    for (int j = 0; j < 10; j++) {
        float hj = b1[j];
#pragma unroll
        for (int i = 0; i < HEADS; i++) hj += o[i] * W1[i * 10 + j];
        hj = fmaxf(hj, 0.0f);
        y += hj * W2[j];
    }
    out[idx] = fmaxf(y, 0.0f);
}

// ---------------------------------------------------------------------------
extern "C" void kernel_launch(void* const* d_in, const int* in_sizes, int n_in,
                              void* d_out, int out_size)
{
    const float* query = (const float*)d_in[0];
    const float* key   = (const float*)d_in[1];
    const float* value = (const float*)d_in[2];
    const float* Wq    = (const float*)d_in[3];
    const float* bq    = (const float*)d_in[4];
    const float* Wk    = (const float*)d_in[5];
    const float* bk    = (const float*)d_in[6];
    const float* W1    = (const float*)d_in[7];
    const float* b1    = (const float*)d_in[8];
    const float* W2    = (const float*)d_in[9];
    const float* b2    = (const float*)d_in[10];
    float* out = (float*)d_out;

    __nv_bfloat16 *qh, *ql, *kh, *kl, *wqh, *wql, *wkh, *wkl;
    __nv_bfloat16 *qah, *qal, *kah, *kal;
    cudaGetSymbolAddress((void**)&qh,  g_qh);
    cudaGetSymbolAddress((void**)&ql,  g_ql);
    cudaGetSymbolAddress((void**)&kh,  g_kh);
    cudaGetSymbolAddress((void**)&kl,  g_kl);
    cudaGetSymbolAddress((void**)&wqh, g_wqh);
    cudaGetSymbolAddress((void**)&wql, g_wql);
    cudaGetSymbolAddress((void**)&wkh, g_wkh);
    cudaGetSymbolAddress((void**)&wkl, g_wkl);
    cudaGetSymbolAddress((void**)&qah, g_qah);
    cudaGetSymbolAddress((void**)&qal, g_qal);
    cudaGetSymbolAddress((void**)&kah, g_kah);
    cudaGetSymbolAddress((void**)&kal, g_kal);

    // splits: inputs row-major padded cols; weights [Kp][NP] with padded rows+cols
    split_bf16<<<B_ * LQ_, 256>>>(query, qh, ql, B_ * LQ_, QIN, KPQ);
    split_bf16<<<B_ * LK_, 256>>>(key,   kh, kl, B_ * LK_, KIN, KPK);
    split_bf16<<<KPQ,      256>>>(Wq,  wqh, wql, QIN, PROJ_, NP);
    split_bf16<<<KPK,      256>>>(Wk,  wkh, wkl, KIN, PROJ_, NP);

    cudaFuncSetAttribute(gemm_bf16x3,
                         cudaFuncAttributeMaxDynamicSharedMemorySize, GEMM_SMEM);

    // q projection -> g_qah/g_qal (seqshift 11)
    {
        dim3 grid(NP / BN, (B_ * LQ_) / BM);
        gemm_bf16x3<<<grid, 256, GEMM_SMEM>>>(qh, ql, wqh, wql, bq,
                                              qah, qal, KPQ, 11);
    }
    // k projection -> g_kah/g_kal (seqshift 10)
    {
        dim3 grid(NP / BN, (B_ * LK_) / BM);
        gemm_bf16x3<<<grid, 256, GEMM_SMEM>>>(kh, kl, wkh, wkl, bk,
                                              kah, kal, KPK, 10);
    }
    // tensor-core attention
    {
        cudaFuncSetAttribute(attn_tc,
                             cudaFuncAttributeMaxDynamicSharedMemorySize, ATT_SMEM);
        dim3 grid(LQ_ / 128, HEADS, B_);
        attn_tc<<<grid, 256, ATT_SMEM>>>(value);
    }
    // MLP head
    {
        int n = B_ * LQ_;
        mlp_kernel<<<(n + 255) / 256, 256>>>(W1, b1, W2, b2, out);
    }
}

// round 8
// speedup vs baseline: 3.5355x; 1.0068x over previous
#include <cuda_runtime.h>
#include <cuda_bf16.h>
#include <math.h>

#define B_    8
#define LQ_   2048
#define LK_   1024
#define QIN   1124
#define KIN   10100
#define PROJ_ 500
#define HEADS 10
#define HD    50

#define KPQ   1152   // QIN padded
#define KPK   10112  // KIN padded
#define NP    512    // PROJ padded
#define HDP   64     // head_dim padded for MMA

typedef unsigned int u32;

// ---------------- scratch (allocation-free; zero-initialized) ----------------
__device__ float g_attn[B_ * LQ_ * HEADS];

__device__ __nv_bfloat16 g_qh[B_ * LQ_ * KPQ];   // split inputs
__device__ __nv_bfloat16 g_ql[B_ * LQ_ * KPQ];
__device__ __nv_bfloat16 g_kh[B_ * LK_ * KPK];
__device__ __nv_bfloat16 g_kl[B_ * LK_ * KPK];
__device__ __nv_bfloat16 g_wqh[KPQ * NP];        // W [Kp][NP] row-major
__device__ __nv_bfloat16 g_wql[KPQ * NP];
__device__ __nv_bfloat16 g_wkh[KPK * NP];
__device__ __nv_bfloat16 g_wkl[KPK * NP];

// projected q/k in attention layout [b, head, seq, HDP], bf16 hi/lo
// pad columns [50,64) are never written -> stay zero (device globals zero-init)
__device__ __nv_bfloat16 g_qah[B_ * HEADS * LQ_ * HDP];
__device__ __nv_bfloat16 g_qal[B_ * HEADS * LQ_ * HDP];
__device__ __nv_bfloat16 g_kah[B_ * HEADS * LK_ * HDP];
__device__ __nv_bfloat16 g_kal[B_ * HEADS * LK_ * HDP];

// ------- fp32 -> (hi,lo) bf16 split (row-major, padded rows AND cols) -------
__global__ void split_bf16(const float* __restrict__ X,
                           __nv_bfloat16* __restrict__ H,
                           __nv_bfloat16* __restrict__ L,
                           int rows, int cols, int colsp)
{
    int r = blockIdx.x;
    bool rv = (r < rows);
    for (int c = threadIdx.x; c < colsp; c += blockDim.x) {
        float x = (rv && c < cols) ? X[(size_t)r * cols + c] : 0.0f;
        __nv_bfloat16 h = __float2bfloat16(x);
        size_t o = (size_t)r * colsp + c;
        H[o] = h;
        L[o] = __float2bfloat16(x - __bfloat162float(h));
    }
}

// ---------------- mma / ldmatrix / cp.async helpers ----------------
__device__ __forceinline__ void ldsm_x4(u32* r, u32 addr) {
    asm volatile("ldmatrix.sync.aligned.m8n8.x4.shared.b16 {%0,%1,%2,%3}, [%4];"
        : "=r"(r[0]), "=r"(r[1]), "=r"(r[2]), "=r"(r[3]) : "r"(addr));
}
__device__ __forceinline__ void ldsm_x4_t(u32* r, u32 addr) {
    asm volatile("ldmatrix.sync.aligned.m8n8.x4.trans.shared.b16 {%0,%1,%2,%3}, [%4];"
        : "=r"(r[0]), "=r"(r[1]), "=r"(r[2]), "=r"(r[3]) : "r"(addr));
}
__device__ __forceinline__ void mma_bf16(float* d, const u32* a, const u32* b) {
    asm volatile(
        "mma.sync.aligned.m16n8k16.row.col.f32.bf16.bf16.f32 "
        "{%0,%1,%2,%3},{%4,%5,%6,%7},{%8,%9},{%0,%1,%2,%3};"
        : "+f"(d[0]), "+f"(d[1]), "+f"(d[2]), "+f"(d[3])
        : "r"(a[0]), "r"(a[1]), "r"(a[2]), "r"(a[3]), "r"(b[0]), "r"(b[1]));
}
__device__ __forceinline__ void cp16(u32 dst, const void* src) {
    asm volatile("cp.async.cg.shared.global [%0], [%1], 16;"
                 :: "r"(dst), "l"(src));
}
__device__ __forceinline__ void cp_commit() {
    asm volatile("cp.async.commit_group;" ::: "memory");
}
template <int N>
__device__ __forceinline__ void cp_wait() {
    asm volatile("cp.async.wait_group %0;" :: "n"(N) : "memory");
}

// ------- bf16x3 GEMM v5: cp.async pipeline, 128x128 CTA tile ---------------
// A:[M][Kp] hi/lo row-major; W:[Kp][NP] hi/lo row-major (trans ldmatrix).
// 8 warps (4m x 2n), warp tile 32x64, acc 64 regs. Epilogue -> attention layout.
#define BM  128
#define BN  128
#define BKB 32
#define AST 40                       // smem stride (bf16): 32 k + 8 pad
#define WST 136                      // smem stride (bf16): 128 n + 8 pad
#define A_BUF (BM * AST)             // 5120 elems / 10240 B
#define W_BUF (BKB * WST)            // 4352 elems / 8704 B
#define GEMM_SMEM ((4 * A_BUF + 4 * W_BUF) * 2)   // 75776 B

__global__ __launch_bounds__(256, 2) void gemm_bf16x3(
    const __nv_bfloat16* __restrict__ Ah, const __nv_bfloat16* __restrict__ Al,
    const __nv_bfloat16* __restrict__ Wh, const __nv_bfloat16* __restrict__ Wl,
    const float* __restrict__ bias,
    __nv_bfloat16* __restrict__ DH, __nv_bfloat16* __restrict__ DL,
    int Kp, int seqshift)
{
    extern __shared__ __nv_bfloat16 sm[];
    __nv_bfloat16* sAh = sm;                       // 2 buffers
    __nv_bfloat16* sAl = sm + 2 * A_BUF;
    __nv_bfloat16* sWh = sm + 4 * A_BUF;
    __nv_bfloat16* sWl = sm + 4 * A_BUF + 2 * W_BUF;
    const u32 bAh0 = (u32)__cvta_generic_to_shared(sAh);
    const u32 bAl0 = (u32)__cvta_generic_to_shared(sAl);
    const u32 bWh0 = (u32)__cvta_generic_to_shared(sWh);
    const u32 bWl0 = (u32)__cvta_generic_to_shared(sWl);

    const int t    = threadIdx.x;
    const int lane = t & 31;
    const int warp = t >> 5;
    const int wm   = warp >> 1;       // 0..3 -> 32 m-rows
    const int wn   = warp & 1;        // 0..1 -> 64 n-cols
    const int m0   = blockIdx.y * BM;
    const int n0   = blockIdx.x * BN;

    // cp.async mappings
    const int ar = t >> 1;            // A: rows 0..127, 2 chunks each (i=0,1)
    const int ac = (t & 1) * 2;       // chunk base 0 or 2 (advance +1)
    const int wr = t >> 3;            // W: rows 0..31, chunks (t&7), +8
    const int wc = t & 7;

    auto load_tile = [&](int buf, int k0) {
        // A: 128 rows x 4 chunks(16B) per matrix
#pragma unroll
        for (int i = 0; i < 2; i++) {
            int ch = ac + i;
            size_t g = (size_t)(m0 + ar) * Kp + k0 + ch * 8;
            u32 s = (u32)((buf * A_BUF + ar * AST + ch * 8) * 2);
            cp16(bAh0 + s, Ah + g);
            cp16(bAl0 + s, Al + g);
        }
        // W: 32 rows x 16 chunks(16B) per matrix
#pragma unroll
        for (int i = 0; i < 2; i++) {
            int ch = wc + i * 8;
            size_t g = (size_t)(k0 + wr) * NP + n0 + ch * 8;
            u32 s = (u32)((buf * W_BUF + wr * WST + ch * 8) * 2);
            cp16(bWh0 + s, Wh + g);
            cp16(bWl0 + s, Wl + g);
        }
        cp_commit();
    };

    float acc[2][8][4];
#pragma unroll
    for (int mt = 0; mt < 2; mt++)
#pragma unroll
        for (int nt = 0; nt < 8; nt++)
#pragma unroll
            for (int e = 0; e < 4; e++) acc[mt][nt][e] = 0.0f;

    const int lrow = lane & 15;
    const int lcol = lane >> 4;
    const int ntiles = Kp / BKB;

    load_tile(0, 0);
    if (ntiles > 1) load_tile(1, BKB);

    for (int tl = 0; tl < ntiles; ++tl) {
        const int cur = tl & 1;
        if (tl + 1 < ntiles) cp_wait<1>(); else cp_wait<0>();
        __syncthreads();

        const u32 aHb = bAh0 + cur * A_BUF * 2;
        const u32 aLb = bAl0 + cur * A_BUF * 2;
        const u32 wHb = bWh0 + cur * W_BUF * 2;
        const u32 wLb = bWl0 + cur * W_BUF * 2;

#pragma unroll
        for (int kk = 0; kk < 2; kk++) {
            u32 aH[2][4], aL[2][4];
#pragma unroll
            for (int mt = 0; mt < 2; mt++) {
                u32 off = ((wm * 32 + mt * 16 + lrow) * AST + kk * 16 + lcol * 8) * 2;
                ldsm_x4(aH[mt], aHb + off);
                ldsm_x4(aL[mt], aLb + off);
            }
#pragma unroll
            for (int nq = 0; nq < 4; nq++) {
                u32 bH[4], bL[4];
                u32 off = ((kk * 16 + lrow) * WST + wn * 64 + nq * 16 + lcol * 8) * 2;
                ldsm_x4_t(bH, wHb + off);
                ldsm_x4_t(bL, wLb + off);
#pragma unroll
                for (int mt = 0; mt < 2; mt++) {
                    mma_bf16(acc[mt][2 * nq],     aH[mt], bH);
                    mma_bf16(acc[mt][2 * nq],     aH[mt], bL);
                    mma_bf16(acc[mt][2 * nq],     aL[mt], bH);
                    mma_bf16(acc[mt][2 * nq + 1], aH[mt], bH + 2);
                    mma_bf16(acc[mt][2 * nq + 1], aH[mt], bL + 2);
                    mma_bf16(acc[mt][2 * nq + 1], aL[mt], bH + 2);
                }
            }
        }

        __syncthreads();
        if (tl + 2 < ntiles) load_tile(cur, (tl + 2) * BKB);
    }

    // epilogue: write bf16 hi/lo into [b, head, seq, HDP]
    const int seqlen = 1 << seqshift;
#pragma unroll
    for (int mt = 0; mt < 2; mt++) {
#pragma unroll
        for (int nt = 0; nt < 8; nt++) {
            int row = wm * 32 + mt * 16 + (lane >> 2);
            int col = wn * 64 + nt * 8 + (lane & 3) * 2;
#pragma unroll
            for (int e = 0; e < 4; e++) {
                int m = m0 + row + ((e >> 1) ? 8 : 0);
                int n = n0 + col + (e & 1);
                if (n >= PROJ_) continue;
                int head = n / HD;
                int c    = n - head * HD;
                int bi   = m >> seqshift;
                int si   = m & (seqlen - 1);
                float x = acc[mt][nt][e] + bias[n];
                __nv_bfloat16 h = __float2bfloat16(x);
                size_t o = ((size_t)(bi * HEADS + head) * seqlen + si) * HDP + c;
                DH[o] = h;
                DL[o] = __float2bfloat16(x - __bfloat162float(h));
            }
        }
    }
}

// ---------------- tensor-core attention (R7-proven) ----------------
#define ATT_ST 72
#define QH_OFF 0
#define QL_OFF (128 * ATT_ST * 2)
#define KH_OFF (2 * QL_OFF)
#define KL_OFF (3 * QL_OFF)
#define V_OFF  (4 * QL_OFF)
#define ATT_SMEM (V_OFF + 128 * 4)

__global__ __launch_bounds__(256, 2) void attn_tc(const float* __restrict__ value)
{
    extern __shared__ char smc[];
    const u32 sb = (u32)__cvta_generic_to_shared(smc);
    float* vsh = (float*)(smc + V_OFF);

    const int b  = blockIdx.z;
    const int h  = blockIdx.y;
    const int q0 = blockIdx.x * 128;
    const int t  = threadIdx.x;
    const int lane = t & 31;
    const int w    = t >> 5;

    {
        const __nv_bfloat16* qh = g_qah + ((size_t)(b * HEADS + h) * LQ_ + q0) * HDP;
        const __nv_bfloat16* ql = g_qal + ((size_t)(b * HEADS + h) * LQ_ + q0) * HDP;
#pragma unroll
        for (int i = 0; i < 4; i++) {
            int idx = t + i * 256;
            int r = idx >> 3, c = idx & 7;
            uint4 vh = *(const uint4*)(qh + (size_t)r * HDP + c * 8);
            uint4 vl = *(const uint4*)(ql + (size_t)r * HDP + c * 8);
            *(uint4*)(smc + QH_OFF + (r * ATT_ST + c * 8) * 2) = vh;
            *(uint4*)(smc + QL_OFF + (r * ATT_ST + c * 8) * 2) = vl;
        }
    }

    float accA[2] = {0.f, 0.f}, accL[2] = {0.f, 0.f};
    const float scale = 0.14142135623730951f;

    const int bg  = lane >> 3;
    const int bi8 = lane & 7;
    const int brow_off = ((bg & 2) ? 8 : 0) + bi8;
    const int bcol_off = (bg & 1) ? 8 : 0;

    for (int kt = 0; kt < LK_; kt += 128) {
        __syncthreads();
        {
            const __nv_bfloat16* kh = g_kah + ((size_t)(b * HEADS + h) * LK_ + kt) * HDP;
            const __nv_bfloat16* kl = g_kal + ((size_t)(b * HEADS + h) * LK_ + kt) * HDP;
#pragma unroll
            for (int i = 0; i < 4; i++) {
                int idx = t + i * 256;
                int r = idx >> 3, c = idx & 7;
                uint4 vh = *(const uint4*)(kh + (size_t)r * HDP + c * 8);
                uint4 vl = *(const uint4*)(kl + (size_t)r * HDP + c * 8);
                *(uint4*)(smc + KH_OFF + (r * ATT_ST + c * 8) * 2) = vh;
                *(uint4*)(smc + KL_OFF + (r * ATT_ST + c * 8) * 2) = vl;
            }
            if (t < 128) vsh[t] = value[b * LK_ + kt + t];
        }
        __syncthreads();

#pragma unroll
        for (int half = 0; half < 2; half++) {
            float S[8][4];
#pragma unroll
            for (int nt = 0; nt < 8; nt++)
#pragma unroll
                for (int e = 0; e < 4; e++) S[nt][e] = 0.0f;

#pragma unroll
            for (int ks = 0; ks < 4; ks++) {
                const int k0 = ks * 16;
                u32 aH[4], aL[4];
                {
                    u32 off = ((w * 16 + (lane & 15)) * ATT_ST + k0 + (lane >> 4) * 8) * 2;
                    ldsm_x4(aH, sb + QH_OFF + off);
                    ldsm_x4(aL, sb + QL_OFF + off);
                }
#pragma unroll
                for (int ng2 = 0; ng2 < 4; ng2++) {
                    const int ng = half * 4 + ng2;
                    u32 bH[4], bL[4];
                    u32 off = ((ng * 16 + brow_off) * ATT_ST + k0 + bcol_off) * 2;
                    ldsm_x4(bH, sb + KH_OFF + off);
                    ldsm_x4(bL, sb + KL_OFF + off);
                    mma_bf16(S[2 * ng2],     aH, bH);
                    mma_bf16(S[2 * ng2],     aH, bL);
                    mma_bf16(S[2 * ng2],     aL, bH);
                    mma_bf16(S[2 * ng2 + 1], aH, bH + 2);
                    mma_bf16(S[2 * ng2 + 1], aH, bL + 2);
                    mma_bf16(S[2 * ng2 + 1], aL, bH + 2);
                }
            }

#pragma unroll
            for (int nt = 0; nt < 8; nt++) {
                int n = (half * 8 + nt) * 8 + (lane & 3) * 2;
                float v0 = vsh[n], v1 = vsh[n + 1];
                float e0 = __expf(S[nt][0] * scale);
                float e1 = __expf(S[nt][1] * scale);
                float e2 = __expf(S[nt][2] * scale);
                float e3 = __expf(S[nt][3] * scale);
                accA[0] += e0 * v0 + e1 * v1;
                accL[0] += e0 + e1;
                accA[1] += e2 * v0 + e3 * v1;
                accL[1] += e2 + e3;
            }
        }
    }

#pragma unroll
    for (int r = 0; r < 2; r++) {
#pragma unroll
        for (int o = 1; o <= 2; o <<= 1) {
            accA[r] += __shfl_xor_sync(0xffffffffu, accA[r], o);
            accL[r] += __shfl_xor_sync(0xffffffffu, accL[r], o);
        }
    }
    if ((lane & 3) == 0) {
        int row = q0 + w * 16 + (lane >> 2);
        g_attn[((size_t)b * LQ_ + row) * HEADS + h]     = accA[0] / accL[0];
        g_attn[((size_t)b * LQ_ + row + 8) * HEADS + h] = accA[1] / accL[1];
    }
}

// ---------------- tiny MLP ----------------
__global__ __launch_bounds__(256) void mlp_kernel(
    const float* __restrict__ W1, const float* __restrict__ b1,
    const float* __restrict__ W2, const float* __restrict__ b2,
    float* __restrict__ out)
{
    int idx = blockIdx.x * blockDim.x + threadIdx.x;
    if (idx >= B_ * LQ_) return;

    float o[HEADS];
#pragma unroll
    for (int i = 0; i < HEADS; i++) o[i] = g_attn[(size_t)idx * HEADS + i];

    float y = b2[0];
#pragma unroll
    for (int j = 0; j < 10; j++) {
        float hj = b1[j];
#pragma unroll
        for (int i = 0; i < HEADS; i++) hj += o[i] * W1[i * 10 + j];
        hj = fmaxf(hj, 0.0f);
        y += hj * W2[j];
    }
    out[idx] = fmaxf(y, 0.0f);
}

// ---------------------------------------------------------------------------
extern "C" void kernel_launch(void* const* d_in, const int* in_sizes, int n_in,
                              void* d_out, int out_size)
{
    const float* query = (const float*)d_in[0];
    const float* key   = (const float*)d_in[1];
    const float* value = (const float*)d_in[2];
    const float* Wq    = (const float*)d_in[3];
    const float* bq    = (const float*)d_in[4];
    const float* Wk    = (const float*)d_in[5];
    const float* bk    = (const float*)d_in[6];
    const float* W1    = (const float*)d_in[7];
    const float* b1    = (const float*)d_in[8];
    const float* W2    = (const float*)d_in[9];
    const float* b2    = (const float*)d_in[10];
    float* out = (float*)d_out;

    __nv_bfloat16 *qh, *ql, *kh, *kl, *wqh, *wql, *wkh, *wkl;
    __nv_bfloat16 *qah, *qal, *kah, *kal;
    cudaGetSymbolAddress((void**)&qh,  g_qh);
    cudaGetSymbolAddress((void**)&ql,  g_ql);
    cudaGetSymbolAddress((void**)&kh,  g_kh);
    cudaGetSymbolAddress((void**)&kl,  g_kl);
    cudaGetSymbolAddress((void**)&wqh, g_wqh);
    cudaGetSymbolAddress((void**)&wql, g_wql);
    cudaGetSymbolAddress((void**)&wkh, g_wkh);
    cudaGetSymbolAddress((void**)&wkl, g_wkl);
    cudaGetSymbolAddress((void**)&qah, g_qah);
    cudaGetSymbolAddress((void**)&qal, g_qal);
    cudaGetSymbolAddress((void**)&kah, g_kah);
    cudaGetSymbolAddress((void**)&kal, g_kal);

    split_bf16<<<B_ * LQ_, 256>>>(query, qh, ql, B_ * LQ_, QIN, KPQ);
    split_bf16<<<B_ * LK_, 256>>>(key,   kh, kl, B_ * LK_, KIN, KPK);
    split_bf16<<<KPQ,      256>>>(Wq,  wqh, wql, QIN, PROJ_, NP);
    split_bf16<<<KPK,      256>>>(Wk,  wkh, wkl, KIN, PROJ_, NP);

    cudaFuncSetAttribute(gemm_bf16x3,
                         cudaFuncAttributeMaxDynamicSharedMemorySize, GEMM_SMEM);

    // q projection -> g_qah/g_qal (seqshift 11)
    {
        dim3 grid(NP / BN, (B_ * LQ_) / BM);
        gemm_bf16x3<<<grid, 256, GEMM_SMEM>>>(qh, ql, wqh, wql, bq,
                                              qah, qal, KPQ, 11);
    }
    // k projection -> g_kah/g_kal (seqshift 10)
    {
        dim3 grid(NP / BN, (B_ * LK_) / BM);
        gemm_bf16x3<<<grid, 256, GEMM_SMEM>>>(kh, kl, wkh, wkl, bk,
                                              kah, kal, KPK, 10);
    }
    // tensor-core attention
    {
        cudaFuncSetAttribute(attn_tc,
                             cudaFuncAttributeMaxDynamicSharedMemorySize, ATT_SMEM);
        dim3 grid(LQ_ / 128, HEADS, B_);
        attn_tc<<<grid, 256, ATT_SMEM>>>(value);
    }
    // MLP head
    {
        int n = B_ * LQ_;
        mlp_kernel<<<(n + 255) / 256, 256>>>(W1, b1, W2, b2, out);
    }
}

// round 9
// speedup vs baseline: 3.8157x; 1.0793x over previous
#include <cuda_runtime.h>
#include <cuda_bf16.h>
#include <math.h>

#define B_    8
#define LQ_   2048
#define LK_   1024
#define QIN   1124
#define KIN   10100
#define PROJ_ 500
#define HEADS 10
#define HD    50

#define KPQ   1152   // QIN padded
#define KPK   10112  // KIN padded
#define NP    512    // PROJ padded
#define HDP   64     // head_dim padded for MMA

typedef unsigned int u32;

// ---------------- scratch (allocation-free; zero-initialized) ----------------
__device__ float g_attn[B_ * LQ_ * HEADS];

__device__ __nv_bfloat16 g_qh[B_ * LQ_ * KPQ];   // split inputs
__device__ __nv_bfloat16 g_ql[B_ * LQ_ * KPQ];
__device__ __nv_bfloat16 g_kh[B_ * LK_ * KPK];
__device__ __nv_bfloat16 g_kl[B_ * LK_ * KPK];
__device__ __nv_bfloat16 g_wqh[KPQ * NP];        // W [Kp][NP] row-major
__device__ __nv_bfloat16 g_wql[KPQ * NP];
__device__ __nv_bfloat16 g_wkh[KPK * NP];
__device__ __nv_bfloat16 g_wkl[KPK * NP];

// projected q/k in attention layout [b, head, seq, HDP], bf16 hi/lo
// pad columns [50,64) are never written -> stay zero (device globals zero-init)
__device__ __nv_bfloat16 g_qah[B_ * HEADS * LQ_ * HDP];
__device__ __nv_bfloat16 g_qal[B_ * HEADS * LQ_ * HDP];
__device__ __nv_bfloat16 g_kah[B_ * HEADS * LK_ * HDP];
__device__ __nv_bfloat16 g_kal[B_ * HEADS * LK_ * HDP];

// ------- fp32 -> (hi,lo) bf16 split, vectorized: 8 cols/thread --------------
// Loads: 2x float4 (guarded at edges); stores: 1x uint4 each for H and L.
// Requires colsp % 8 == 0 and cols % 4 == 0 (true for all four uses).
__device__ __forceinline__ u32 pack_bf2(__nv_bfloat16 lo, __nv_bfloat16 hi) {
    return (u32)__bfloat16_as_ushort(lo) | ((u32)__bfloat16_as_ushort(hi) << 16);
}
__global__ void split_bf16_v(const float* __restrict__ X,
                             __nv_bfloat16* __restrict__ H,
                             __nv_bfloat16* __restrict__ L,
                             int rows, int cols, int colsp)
{
    int r = blockIdx.x;
    bool rv = (r < rows);
    const float* Xr = X + (size_t)r * cols;
    for (int c8 = threadIdx.x * 8; c8 < colsp; c8 += blockDim.x * 8) {
        float x[8];
        if (rv && c8 + 8 <= cols) {
            float4 a = *(const float4*)(Xr + c8);
            float4 b = *(const float4*)(Xr + c8 + 4);
            x[0] = a.x; x[1] = a.y; x[2] = a.z; x[3] = a.w;
            x[4] = b.x; x[5] = b.y; x[6] = b.z; x[7] = b.w;
        } else {
#pragma unroll
            for (int i = 0; i < 8; i++) {
                int c = c8 + i;
                x[i] = (rv && c < cols) ? Xr[c] : 0.0f;
            }
        }
        __nv_bfloat16 hb[8], lb[8];
#pragma unroll
        for (int i = 0; i < 8; i++) {
            hb[i] = __float2bfloat16(x[i]);
            lb[i] = __float2bfloat16(x[i] - __bfloat162float(hb[i]));
        }
        size_t o = (size_t)r * colsp + c8;
        uint4 hv, lv;
        hv.x = pack_bf2(hb[0], hb[1]); hv.y = pack_bf2(hb[2], hb[3]);
        hv.z = pack_bf2(hb[4], hb[5]); hv.w = pack_bf2(hb[6], hb[7]);
        lv.x = pack_bf2(lb[0], lb[1]); lv.y = pack_bf2(lb[2], lb[3]);
        lv.z = pack_bf2(lb[4], lb[5]); lv.w = pack_bf2(lb[6], lb[7]);
        *(uint4*)(H + o) = hv;
        *(uint4*)(L + o) = lv;
    }
}

// ---------------- mma / ldmatrix / cp.async helpers ----------------
__device__ __forceinline__ void ldsm_x4(u32* r, u32 addr) {
    asm volatile("ldmatrix.sync.aligned.m8n8.x4.shared.b16 {%0,%1,%2,%3}, [%4];"
        : "=r"(r[0]), "=r"(r[1]), "=r"(r[2]), "=r"(r[3]) : "r"(addr));
}
__device__ __forceinline__ void ldsm_x4_t(u32* r, u32 addr) {
    asm volatile("ldmatrix.sync.aligned.m8n8.x4.trans.shared.b16 {%0,%1,%2,%3}, [%4];"
        : "=r"(r[0]), "=r"(r[1]), "=r"(r[2]), "=r"(r[3]) : "r"(addr));
}
__device__ __forceinline__ void mma_bf16(float* d, const u32* a, const u32* b) {
    asm volatile(
        "mma.sync.aligned.m16n8k16.row.col.f32.bf16.bf16.f32 "
        "{%0,%1,%2,%3},{%4,%5,%6,%7},{%8,%9},{%0,%1,%2,%3};"
        : "+f"(d[0]), "+f"(d[1]), "+f"(d[2]), "+f"(d[3])
        : "r"(a[0]), "r"(a[1]), "r"(a[2]), "r"(a[3]), "r"(b[0]), "r"(b[1]));
}
__device__ __forceinline__ void cp16(u32 dst, const void* src) {
    asm volatile("cp.async.cg.shared.global [%0], [%1], 16;"
                 :: "r"(dst), "l"(src));
}
__device__ __forceinline__ void cp_commit() {
    asm volatile("cp.async.commit_group;" ::: "memory");
}
template <int N>
__device__ __forceinline__ void cp_wait() {
    asm volatile("cp.async.wait_group %0;" :: "n"(N) : "memory");
}

// ------- bf16x3 GEMM v5 (R8): cp.async pipeline, 128x128 CTA tile ----------
#define BM  128
#define BN  128
#define BKB 32
#define AST 40
#define WST 136
#define A_BUF (BM * AST)
#define W_BUF (BKB * WST)
#define GEMM_SMEM ((4 * A_BUF + 4 * W_BUF) * 2)   // 75776 B

__global__ __launch_bounds__(256, 2) void gemm_bf16x3(
    const __nv_bfloat16* __restrict__ Ah, const __nv_bfloat16* __restrict__ Al,
    const __nv_bfloat16* __restrict__ Wh, const __nv_bfloat16* __restrict__ Wl,
    const float* __restrict__ bias,
    __nv_bfloat16* __restrict__ DH, __nv_bfloat16* __restrict__ DL,
    int Kp, int seqshift)
{
    extern __shared__ __nv_bfloat16 sm[];
    __nv_bfloat16* sAh = sm;
    __nv_bfloat16* sAl = sm + 2 * A_BUF;
    __nv_bfloat16* sWh = sm + 4 * A_BUF;
    __nv_bfloat16* sWl = sm + 4 * A_BUF + 2 * W_BUF;
    const u32 bAh0 = (u32)__cvta_generic_to_shared(sAh);
    const u32 bAl0 = (u32)__cvta_generic_to_shared(sAl);
    const u32 bWh0 = (u32)__cvta_generic_to_shared(sWh);
    const u32 bWl0 = (u32)__cvta_generic_to_shared(sWl);

    const int t    = threadIdx.x;
    const int lane = t & 31;
    const int warp = t >> 5;
    const int wm   = warp >> 1;
    const int wn   = warp & 1;
    const int m0   = blockIdx.y * BM;
    const int n0   = blockIdx.x * BN;

    const int ar = t >> 1;
    const int ac = (t & 1) * 2;
    const int wr = t >> 3;
    const int wc = t & 7;

    auto load_tile = [&](int buf, int k0) {
#pragma unroll
        for (int i = 0; i < 2; i++) {
            int ch = ac + i;
            size_t g = (size_t)(m0 + ar) * Kp + k0 + ch * 8;
            u32 s = (u32)((buf * A_BUF + ar * AST + ch * 8) * 2);
            cp16(bAh0 + s, Ah + g);
            cp16(bAl0 + s, Al + g);
        }
#pragma unroll
        for (int i = 0; i < 2; i++) {
            int ch = wc + i * 8;
            size_t g = (size_t)(k0 + wr) * NP + n0 + ch * 8;
            u32 s = (u32)((buf * W_BUF + wr * WST + ch * 8) * 2);
            cp16(bWh0 + s, Wh + g);
            cp16(bWl0 + s, Wl + g);
        }
        cp_commit();
    };

    float acc[2][8][4];
#pragma unroll
    for (int mt = 0; mt < 2; mt++)
#pragma unroll
        for (int nt = 0; nt < 8; nt++)
#pragma unroll
            for (int e = 0; e < 4; e++) acc[mt][nt][e] = 0.0f;

    const int lrow = lane & 15;
    const int lcol = lane >> 4;
    const int ntiles = Kp / BKB;

    load_tile(0, 0);
    if (ntiles > 1) load_tile(1, BKB);

    for (int tl = 0; tl < ntiles; ++tl) {
        const int cur = tl & 1;
        if (tl + 1 < ntiles) cp_wait<1>(); else cp_wait<0>();
        __syncthreads();

        const u32 aHb = bAh0 + cur * A_BUF * 2;
        const u32 aLb = bAl0 + cur * A_BUF * 2;
        const u32 wHb = bWh0 + cur * W_BUF * 2;
        const u32 wLb = bWl0 + cur * W_BUF * 2;

#pragma unroll
        for (int kk = 0; kk < 2; kk++) {
            u32 aH[2][4], aL[2][4];
#pragma unroll
            for (int mt = 0; mt < 2; mt++) {
                u32 off = ((wm * 32 + mt * 16 + lrow) * AST + kk * 16 + lcol * 8) * 2;
                ldsm_x4(aH[mt], aHb + off);
                ldsm_x4(aL[mt], aLb + off);
            }
#pragma unroll
            for (int nq = 0; nq < 4; nq++) {
                u32 bH[4], bL[4];
                u32 off = ((kk * 16 + lrow) * WST + wn * 64 + nq * 16 + lcol * 8) * 2;
                ldsm_x4_t(bH, wHb + off);
                ldsm_x4_t(bL, wLb + off);
#pragma unroll
                for (int mt = 0; mt < 2; mt++) {
                    mma_bf16(acc[mt][2 * nq],     aH[mt], bH);
                    mma_bf16(acc[mt][2 * nq],     aH[mt], bL);
                    mma_bf16(acc[mt][2 * nq],     aL[mt], bH);
                    mma_bf16(acc[mt][2 * nq + 1], aH[mt], bH + 2);
                    mma_bf16(acc[mt][2 * nq + 1], aH[mt], bL + 2);
                    mma_bf16(acc[mt][2 * nq + 1], aL[mt], bH + 2);
                }
            }
        }

        __syncthreads();
        if (tl + 2 < ntiles) load_tile(cur, (tl + 2) * BKB);
    }

    const int seqlen = 1 << seqshift;
#pragma unroll
    for (int mt = 0; mt < 2; mt++) {
#pragma unroll
        for (int nt = 0; nt < 8; nt++) {
            int row = wm * 32 + mt * 16 + (lane >> 2);
            int col = wn * 64 + nt * 8 + (lane & 3) * 2;
#pragma unroll
            for (int e = 0; e < 4; e++) {
                int m = m0 + row + ((e >> 1) ? 8 : 0);
                int n = n0 + col + (e & 1);
                if (n >= PROJ_) continue;
                int head = n / HD;
                int c    = n - head * HD;
                int bi   = m >> seqshift;
                int si   = m & (seqlen - 1);
                float x = acc[mt][nt][e] + bias[n];
                __nv_bfloat16 h = __float2bfloat16(x);
                size_t o = ((size_t)(bi * HEADS + head) * seqlen + si) * HDP + c;
                DH[o] = h;
                DL[o] = __float2bfloat16(x - __bfloat162float(h));
            }
        }
    }
}

// ---------------- tensor-core attention (R7-proven) ----------------
#define ATT_ST 72
#define QH_OFF 0
#define QL_OFF (128 * ATT_ST * 2)
#define KH_OFF (2 * QL_OFF)
#define KL_OFF (3 * QL_OFF)
#define V_OFF  (4 * QL_OFF)
#define ATT_SMEM (V_OFF + 128 * 4)

__global__ __launch_bounds__(256, 2) void attn_tc(const float* __restrict__ value)
{
    extern __shared__ char smc[];
    const u32 sb = (u32)__cvta_generic_to_shared(smc);
    float* vsh = (float*)(smc + V_OFF);

    const int b  = blockIdx.z;
    const int h  = blockIdx.y;
    const int q0 = blockIdx.x * 128;
    const int t  = threadIdx.x;
    const int lane = t & 31;
    const int w    = t >> 5;

    {
        const __nv_bfloat16* qh = g_qah + ((size_t)(b * HEADS + h) * LQ_ + q0) * HDP;
        const __nv_bfloat16* ql = g_qal + ((size_t)(b * HEADS + h) * LQ_ + q0) * HDP;
#pragma unroll
        for (int i = 0; i < 4; i++) {
            int idx = t + i * 256;
            int r = idx >> 3, c = idx & 7;
            uint4 vh = *(const uint4*)(qh + (size_t)r * HDP + c * 8);
            uint4 vl = *(const uint4*)(ql + (size_t)r * HDP + c * 8);
            *(uint4*)(smc + QH_OFF + (r * ATT_ST + c * 8) * 2) = vh;
            *(uint4*)(smc + QL_OFF + (r * ATT_ST + c * 8) * 2) = vl;
        }
    }

    float accA[2] = {0.f, 0.f}, accL[2] = {0.f, 0.f};
    const float scale = 0.14142135623730951f;

    const int bg  = lane >> 3;
    const int bi8 = lane & 7;
    const int brow_off = ((bg & 2) ? 8 : 0) + bi8;
    const int bcol_off = (bg & 1) ? 8 : 0;

    for (int kt = 0; kt < LK_; kt += 128) {
        __syncthreads();
        {
            const __nv_bfloat16* kh = g_kah + ((size_t)(b * HEADS + h) * LK_ + kt) * HDP;
            const __nv_bfloat16* kl = g_kal + ((size_t)(b * HEADS + h) * LK_ + kt) * HDP;
#pragma unroll
            for (int i = 0; i < 4; i++) {
                int idx = t + i * 256;
                int r = idx >> 3, c = idx & 7;
                uint4 vh = *(const uint4*)(kh + (size_t)r * HDP + c * 8);
                uint4 vl = *(const uint4*)(kl + (size_t)r * HDP + c * 8);
                *(uint4*)(smc + KH_OFF + (r * ATT_ST + c * 8) * 2) = vh;
                *(uint4*)(smc + KL_OFF + (r * ATT_ST + c * 8) * 2) = vl;
            }
            if (t < 128) vsh[t] = value[b * LK_ + kt + t];
        }
        __syncthreads();

#pragma unroll
        for (int half = 0; half < 2; half++) {
            float S[8][4];
#pragma unroll
            for (int nt = 0; nt < 8; nt++)
#pragma unroll
                for (int e = 0; e < 4; e++) S[nt][e] = 0.0f;

#pragma unroll
            for (int ks = 0; ks < 4; ks++) {
                const int k0 = ks * 16;
                u32 aH[4], aL[4];
                {
                    u32 off = ((w * 16 + (lane & 15)) * ATT_ST + k0 + (lane >> 4) * 8) * 2;
                    ldsm_x4(aH, sb + QH_OFF + off);
                    ldsm_x4(aL, sb + QL_OFF + off);
                }
#pragma unroll
                for (int ng2 = 0; ng2 < 4; ng2++) {
                    const int ng = half * 4 + ng2;
                    u32 bH[4], bL[4];
                    u32 off = ((ng * 16 + brow_off) * ATT_ST + k0 + bcol_off) * 2;
                    ldsm_x4(bH, sb + KH_OFF + off);
                    ldsm_x4(bL, sb + KL_OFF + off);
                    mma_bf16(S[2 * ng2],     aH, bH);
                    mma_bf16(S[2 * ng2],     aH, bL);
                    mma_bf16(S[2 * ng2],     aL, bH);
                    mma_bf16(S[2 * ng2 + 1], aH, bH + 2);
                    mma_bf16(S[2 * ng2 + 1], aH, bL + 2);
                    mma_bf16(S[2 * ng2 + 1], aL, bH + 2);
                }
            }

#pragma unroll
            for (int nt = 0; nt < 8; nt++) {
                int n = (half * 8 + nt) * 8 + (lane & 3) * 2;
                float v0 = vsh[n], v1 = vsh[n + 1];
                float e0 = __expf(S[nt][0] * scale);
                float e1 = __expf(S[nt][1] * scale);
                float e2 = __expf(S[nt][2] * scale);
                float e3 = __expf(S[nt][3] * scale);
                accA[0] += e0 * v0 + e1 * v1;
                accL[0] += e0 + e1;
                accA[1] += e2 * v0 + e3 * v1;
                accL[1] += e2 + e3;
            }
        }
    }

#pragma unroll
    for (int r = 0; r < 2; r++) {
#pragma unroll
        for (int o = 1; o <= 2; o <<= 1) {
            accA[r] += __shfl_xor_sync(0xffffffffu, accA[r], o);
            accL[r] += __shfl_xor_sync(0xffffffffu, accL[r], o);
        }
    }
    if ((lane & 3) == 0) {
        int row = q0 + w * 16 + (lane >> 2);
        g_attn[((size_t)b * LQ_ + row) * HEADS + h]     = accA[0] / accL[0];
        g_attn[((size_t)b * LQ_ + row + 8) * HEADS + h] = accA[1] / accL[1];
    }
}

// ---------------- tiny MLP ----------------
__global__ __launch_bounds__(256) void mlp_kernel(
    const float* __restrict__ W1, const float* __restrict__ b1,
    const float* __restrict__ W2, const float* __restrict__ b2,
    float* __restrict__ out)
{
    int idx = blockIdx.x * blockDim.x + threadIdx.x;
    if (idx >= B_ * LQ_) return;

    float o[HEADS];
#pragma unroll
    for (int i = 0; i < HEADS; i++) o[i] = g_attn[(size_t)idx * HEADS + i];

    float y = b2[0];
#pragma unroll
    for (int j = 0; j < 10; j++) {
        float hj = b1[j];
#pragma unroll
        for (int i = 0; i < HEADS; i++) hj += o[i] * W1[i * 10 + j];
        hj = fmaxf(hj, 0.0f);
        y += hj * W2[j];
    }
    out[idx] = fmaxf(y, 0.0f);
}

// ---------------------------------------------------------------------------
extern "C" void kernel_launch(void* const* d_in, const int* in_sizes, int n_in,
                              void* d_out, int out_size)
{
    const float* query = (const float*)d_in[0];
    const float* key   = (const float*)d_in[1];
    const float* value = (const float*)d_in[2];
    const float* Wq    = (const float*)d_in[3];
    const float* bq    = (const float*)d_in[4];
    const float* Wk    = (const float*)d_in[5];
    const float* bk    = (const float*)d_in[6];
    const float* W1    = (const float*)d_in[7];
    const float* b1    = (const float*)d_in[8];
    const float* W2    = (const float*)d_in[9];
    const float* b2    = (const float*)d_in[10];
    float* out = (float*)d_out;

    __nv_bfloat16 *qh, *ql, *kh, *kl, *wqh, *wql, *wkh, *wkl;
    __nv_bfloat16 *qah, *qal, *kah, *kal;
    cudaGetSymbolAddress((void**)&qh,  g_qh);
    cudaGetSymbolAddress((void**)&ql,  g_ql);
    cudaGetSymbolAddress((void**)&kh,  g_kh);
    cudaGetSymbolAddress((void**)&kl,  g_kl);
    cudaGetSymbolAddress((void**)&wqh, g_wqh);
    cudaGetSymbolAddress((void**)&wql, g_wql);
    cudaGetSymbolAddress((void**)&wkh, g_wkh);
    cudaGetSymbolAddress((void**)&wkl, g_wkl);
    cudaGetSymbolAddress((void**)&qah, g_qah);
    cudaGetSymbolAddress((void**)&qal, g_qal);
    cudaGetSymbolAddress((void**)&kah, g_kah);
    cudaGetSymbolAddress((void**)&kal, g_kal);

    split_bf16_v<<<B_ * LQ_, 256>>>(query, qh, ql, B_ * LQ_, QIN, KPQ);
    split_bf16_v<<<B_ * LK_, 256>>>(key,   kh, kl, B_ * LK_, KIN, KPK);
    split_bf16_v<<<KPQ,      64>>>(Wq,  wqh, wql, QIN, PROJ_, NP);
    split_bf16_v<<<KPK,      64>>>(Wk,  wkh, wkl, KIN, PROJ_, NP);

    cudaFuncSetAttribute(gemm_bf16x3,
                         cudaFuncAttributeMaxDynamicSharedMemorySize, GEMM_SMEM);

    // q projection -> g_qah/g_qal (seqshift 11)
    {
        dim3 grid(NP / BN, (B_ * LQ_) / BM);
        gemm_bf16x3<<<grid, 256, GEMM_SMEM>>>(qh, ql, wqh, wql, bq,
                                              qah, qal, KPQ, 11);
    }
    // k projection -> g_kah/g_kal (seqshift 10)
    {
        dim3 grid(NP / BN, (B_ * LK_) / BM);
        gemm_bf16x3<<<grid, 256, GEMM_SMEM>>>(kh, kl, wkh, wkl, bk,
                                              kah, kal, KPK, 10);
    }
    // tensor-core attention
    {
        cudaFuncSetAttribute(attn_tc,
                             cudaFuncAttributeMaxDynamicSharedMemorySize, ATT_SMEM);
        dim3 grid(LQ_ / 128, HEADS, B_);
        attn_tc<<<grid, 256, ATT_SMEM>>>(value);
    }
    // MLP head
    {
        int n = B_ * LQ_;
        mlp_kernel<<<(n + 255) / 256, 256>>>(W1, b1, W2, b2, out);
    }
}

// round 10
// speedup vs baseline: 3.9060x; 1.0237x over previous
#include <cuda_runtime.h>
#include <cuda_bf16.h>
#include <math.h>

#define B_    8
#define LQ_   2048
#define LK_   1024
#define QIN   1124
#define KIN   10100
#define PROJ_ 500
#define HEADS 10
#define HD    50

#define KPQ   1152   // QIN padded
#define KPK   10112  // KIN padded
#define NP    512    // PROJ padded
#define HDP   64     // head_dim padded for MMA

typedef unsigned int u32;

// ---------------- scratch (allocation-free; zero-initialized) ----------------
__device__ float g_attn[B_ * LQ_ * HEADS];

__device__ __nv_bfloat16 g_qh[B_ * LQ_ * KPQ];   // split inputs
__device__ __nv_bfloat16 g_ql[B_ * LQ_ * KPQ];
__device__ __nv_bfloat16 g_kh[B_ * LK_ * KPK];
__device__ __nv_bfloat16 g_kl[B_ * LK_ * KPK];
__device__ __nv_bfloat16 g_wqh[KPQ * NP];        // W [Kp][NP] row-major
__device__ __nv_bfloat16 g_wql[KPQ * NP];
__device__ __nv_bfloat16 g_wkh[KPK * NP];
__device__ __nv_bfloat16 g_wkl[KPK * NP];

// projected q/k in attention layout [b, head, seq, HDP], bf16 hi/lo
// pad columns [50,64) are never written -> stay zero (device globals zero-init)
__device__ __nv_bfloat16 g_qah[B_ * HEADS * LQ_ * HDP];
__device__ __nv_bfloat16 g_qal[B_ * HEADS * LQ_ * HDP];
__device__ __nv_bfloat16 g_kah[B_ * HEADS * LK_ * HDP];
__device__ __nv_bfloat16 g_kal[B_ * HEADS * LK_ * HDP];

// ------- fp32 -> (hi,lo) bf16 split, vectorized: 8 cols/thread --------------
__device__ __forceinline__ u32 pack_bf2(__nv_bfloat16 lo, __nv_bfloat16 hi) {
    return (u32)__bfloat16_as_ushort(lo) | ((u32)__bfloat16_as_ushort(hi) << 16);
}
__global__ void split_bf16_v(const float* __restrict__ X,
                             __nv_bfloat16* __restrict__ H,
                             __nv_bfloat16* __restrict__ L,
                             int rows, int cols, int colsp)
{
    int r = blockIdx.x;
    bool rv = (r < rows);
    const float* Xr = X + (size_t)r * cols;
    for (int c8 = threadIdx.x * 8; c8 < colsp; c8 += blockDim.x * 8) {
        float x[8];
        if (rv && c8 + 8 <= cols) {
            float4 a = *(const float4*)(Xr + c8);
            float4 b = *(const float4*)(Xr + c8 + 4);
            x[0] = a.x; x[1] = a.y; x[2] = a.z; x[3] = a.w;
            x[4] = b.x; x[5] = b.y; x[6] = b.z; x[7] = b.w;
        } else {
#pragma unroll
            for (int i = 0; i < 8; i++) {
                int c = c8 + i;
                x[i] = (rv && c < cols) ? Xr[c] : 0.0f;
            }
        }
        __nv_bfloat16 hb[8], lb[8];
#pragma unroll
        for (int i = 0; i < 8; i++) {
            hb[i] = __float2bfloat16(x[i]);
            lb[i] = __float2bfloat16(x[i] - __bfloat162float(hb[i]));
        }
        size_t o = (size_t)r * colsp + c8;
        uint4 hv, lv;
        hv.x = pack_bf2(hb[0], hb[1]); hv.y = pack_bf2(hb[2], hb[3]);
        hv.z = pack_bf2(hb[4], hb[5]); hv.w = pack_bf2(hb[6], hb[7]);
        lv.x = pack_bf2(lb[0], lb[1]); lv.y = pack_bf2(lb[2], lb[3]);
        lv.z = pack_bf2(lb[4], lb[5]); lv.w = pack_bf2(lb[6], lb[7]);
        *(uint4*)(H + o) = hv;
        *(uint4*)(L + o) = lv;
    }
}

// ---------------- mma / ldmatrix / cp.async helpers ----------------
__device__ __forceinline__ void ldsm_x4(u32* r, u32 addr) {
    asm volatile("ldmatrix.sync.aligned.m8n8.x4.shared.b16 {%0,%1,%2,%3}, [%4];"
        : "=r"(r[0]), "=r"(r[1]), "=r"(r[2]), "=r"(r[3]) : "r"(addr));
}
__device__ __forceinline__ void ldsm_x4_t(u32* r, u32 addr) {
    asm volatile("ldmatrix.sync.aligned.m8n8.x4.trans.shared.b16 {%0,%1,%2,%3}, [%4];"
        : "=r"(r[0]), "=r"(r[1]), "=r"(r[2]), "=r"(r[3]) : "r"(addr));
}
__device__ __forceinline__ void mma_bf16(float* d, const u32* a, const u32* b) {
    asm volatile(
        "mma.sync.aligned.m16n8k16.row.col.f32.bf16.bf16.f32 "
        "{%0,%1,%2,%3},{%4,%5,%6,%7},{%8,%9},{%0,%1,%2,%3};"
        : "+f"(d[0]), "+f"(d[1]), "+f"(d[2]), "+f"(d[3])
        : "r"(a[0]), "r"(a[1]), "r"(a[2]), "r"(a[3]), "r"(b[0]), "r"(b[1]));
}
__device__ __forceinline__ void cp16(u32 dst, const void* src) {
    asm volatile("cp.async.cg.shared.global [%0], [%1], 16;"
                 :: "r"(dst), "l"(src));
}
__device__ __forceinline__ void cp_commit() {
    asm volatile("cp.async.commit_group;" ::: "memory");
}
template <int N>
__device__ __forceinline__ void cp_wait() {
    asm volatile("cp.async.wait_group %0;" :: "n"(N) : "memory");
}

// ------- bf16x3 GEMM (R8-proven): cp.async pipeline, 128x128 CTA tile -------
#define BM  128
#define BN  128
#define BKB 32
#define AST 40
#define WST 136
#define A_BUF (BM * AST)
#define W_BUF (BKB * WST)
#define GEMM_SMEM ((4 * A_BUF + 4 * W_BUF) * 2)   // 75776 B

__global__ __launch_bounds__(256, 2) void gemm_bf16x3(
    const __nv_bfloat16* __restrict__ Ah, const __nv_bfloat16* __restrict__ Al,
    const __nv_bfloat16* __restrict__ Wh, const __nv_bfloat16* __restrict__ Wl,
    const float* __restrict__ bias,
    __nv_bfloat16* __restrict__ DH, __nv_bfloat16* __restrict__ DL,
    int Kp, int seqshift)
{
    extern __shared__ __nv_bfloat16 sm[];
    __nv_bfloat16* sAh = sm;
    __nv_bfloat16* sAl = sm + 2 * A_BUF;
    __nv_bfloat16* sWh = sm + 4 * A_BUF;
    __nv_bfloat16* sWl = sm + 4 * A_BUF + 2 * W_BUF;
    const u32 bAh0 = (u32)__cvta_generic_to_shared(sAh);
    const u32 bAl0 = (u32)__cvta_generic_to_shared(sAl);
    const u32 bWh0 = (u32)__cvta_generic_to_shared(sWh);
    const u32 bWl0 = (u32)__cvta_generic_to_shared(sWl);

    const int t    = threadIdx.x;
    const int lane = t & 31;
    const int warp = t >> 5;
    const int wm   = warp >> 1;
    const int wn   = warp & 1;
    const int m0   = blockIdx.y * BM;
    const int n0   = blockIdx.x * BN;

    const int ar = t >> 1;
    const int ac = (t & 1) * 2;
    const int wr = t >> 3;
    const int wc = t & 7;

    auto load_tile = [&](int buf, int k0) {
#pragma unroll
        for (int i = 0; i < 2; i++) {
            int ch = ac + i;
            size_t g = (size_t)(m0 + ar) * Kp + k0 + ch * 8;
            u32 s = (u32)((buf * A_BUF + ar * AST + ch * 8) * 2);
            cp16(bAh0 + s, Ah + g);
            cp16(bAl0 + s, Al + g);
        }
#pragma unroll
        for (int i = 0; i < 2; i++) {
            int ch = wc + i * 8;
            size_t g = (size_t)(k0 + wr) * NP + n0 + ch * 8;
            u32 s = (u32)((buf * W_BUF + wr * WST + ch * 8) * 2);
            cp16(bWh0 + s, Wh + g);
            cp16(bWl0 + s, Wl + g);
        }
        cp_commit();
    };

    float acc[2][8][4];
#pragma unroll
    for (int mt = 0; mt < 2; mt++)
#pragma unroll
        for (int nt = 0; nt < 8; nt++)
#pragma unroll
            for (int e = 0; e < 4; e++) acc[mt][nt][e] = 0.0f;

    const int lrow = lane & 15;
    const int lcol = lane >> 4;
    const int ntiles = Kp / BKB;

    load_tile(0, 0);
    if (ntiles > 1) load_tile(1, BKB);

    for (int tl = 0; tl < ntiles; ++tl) {
        const int cur = tl & 1;
        if (tl + 1 < ntiles) cp_wait<1>(); else cp_wait<0>();
        __syncthreads();

        const u32 aHb = bAh0 + cur * A_BUF * 2;
        const u32 aLb = bAl0 + cur * A_BUF * 2;
        const u32 wHb = bWh0 + cur * W_BUF * 2;
        const u32 wLb = bWl0 + cur * W_BUF * 2;

#pragma unroll
        for (int kk = 0; kk < 2; kk++) {
            u32 aH[2][4], aL[2][4];
#pragma unroll
            for (int mt = 0; mt < 2; mt++) {
                u32 off = ((wm * 32 + mt * 16 + lrow) * AST + kk * 16 + lcol * 8) * 2;
                ldsm_x4(aH[mt], aHb + off);
                ldsm_x4(aL[mt], aLb + off);
            }
#pragma unroll
            for (int nq = 0; nq < 4; nq++) {
                u32 bH[4], bL[4];
                u32 off = ((kk * 16 + lrow) * WST + wn * 64 + nq * 16 + lcol * 8) * 2;
                ldsm_x4_t(bH, wHb + off);
                ldsm_x4_t(bL, wLb + off);
#pragma unroll
                for (int mt = 0; mt < 2; mt++) {
                    mma_bf16(acc[mt][2 * nq],     aH[mt], bH);
                    mma_bf16(acc[mt][2 * nq],     aH[mt], bL);
                    mma_bf16(acc[mt][2 * nq],     aL[mt], bH);
                    mma_bf16(acc[mt][2 * nq + 1], aH[mt], bH + 2);
                    mma_bf16(acc[mt][2 * nq + 1], aH[mt], bL + 2);
                    mma_bf16(acc[mt][2 * nq + 1], aL[mt], bH + 2);
                }
            }
        }

        __syncthreads();
        if (tl + 2 < ntiles) load_tile(cur, (tl + 2) * BKB);
    }

    const int seqlen = 1 << seqshift;
#pragma unroll
    for (int mt = 0; mt < 2; mt++) {
#pragma unroll
        for (int nt = 0; nt < 8; nt++) {
            int row = wm * 32 + mt * 16 + (lane >> 2);
            int col = wn * 64 + nt * 8 + (lane & 3) * 2;
#pragma unroll
            for (int e = 0; e < 4; e++) {
                int m = m0 + row + ((e >> 1) ? 8 : 0);
                int n = n0 + col + (e & 1);
                if (n >= PROJ_) continue;
                int head = n / HD;
                int c    = n - head * HD;
                int bi   = m >> seqshift;
                int si   = m & (seqlen - 1);
                float x = acc[mt][nt][e] + bias[n];
                __nv_bfloat16 h = __float2bfloat16(x);
                size_t o = ((size_t)(bi * HEADS + head) * seqlen + si) * HDP + c;
                DH[o] = h;
                DL[o] = __float2bfloat16(x - __bfloat162float(h));
            }
        }
    }
}

// ---------------- tensor-core attention (R7-proven) ----------------
#define ATT_ST 72
#define QH_OFF 0
#define QL_OFF (128 * ATT_ST * 2)
#define KH_OFF (2 * QL_OFF)
#define KL_OFF (3 * QL_OFF)
#define V_OFF  (4 * QL_OFF)
#define ATT_SMEM (V_OFF + 128 * 4)

__global__ __launch_bounds__(256, 2) void attn_tc(const float* __restrict__ value)
{
    extern __shared__ char smc[];
    const u32 sb = (u32)__cvta_generic_to_shared(smc);
    float* vsh = (float*)(smc + V_OFF);

    const int b  = blockIdx.z;
    const int h  = blockIdx.y;
    const int q0 = blockIdx.x * 128;
    const int t  = threadIdx.x;
    const int lane = t & 31;
    const int w    = t >> 5;

    {
        const __nv_bfloat16* qh = g_qah + ((size_t)(b * HEADS + h) * LQ_ + q0) * HDP;
        const __nv_bfloat16* ql = g_qal + ((size_t)(b * HEADS + h) * LQ_ + q0) * HDP;
#pragma unroll
        for (int i = 0; i < 4; i++) {
            int idx = t + i * 256;
            int r = idx >> 3, c = idx & 7;
            uint4 vh = *(const uint4*)(qh + (size_t)r * HDP + c * 8);
            uint4 vl = *(const uint4*)(ql + (size_t)r * HDP + c * 8);
            *(uint4*)(smc + QH_OFF + (r * ATT_ST + c * 8) * 2) = vh;
            *(uint4*)(smc + QL_OFF + (r * ATT_ST + c * 8) * 2) = vl;
        }
    }

    float accA[2] = {0.f, 0.f}, accL[2] = {0.f, 0.f};
    const float scale = 0.14142135623730951f;

    const int bg  = lane >> 3;
    const int bi8 = lane & 7;
    const int brow_off = ((bg & 2) ? 8 : 0) + bi8;
    const int bcol_off = (bg & 1) ? 8 : 0;

    for (int kt = 0; kt < LK_; kt += 128) {
        __syncthreads();
        {
            const __nv_bfloat16* kh = g_kah + ((size_t)(b * HEADS + h) * LK_ + kt) * HDP;
            const __nv_bfloat16* kl = g_kal + ((size_t)(b * HEADS + h) * LK_ + kt) * HDP;
#pragma unroll
            for (int i = 0; i < 4; i++) {
                int idx = t + i * 256;
                int r = idx >> 3, c = idx & 7;
                uint4 vh = *(const uint4*)(kh + (size_t)r * HDP + c * 8);
                uint4 vl = *(const uint4*)(kl + (size_t)r * HDP + c * 8);
                *(uint4*)(smc + KH_OFF + (r * ATT_ST + c * 8) * 2) = vh;
                *(uint4*)(smc + KL_OFF + (r * ATT_ST + c * 8) * 2) = vl;
            }
            if (t < 128) vsh[t] = value[b * LK_ + kt + t];
        }
        __syncthreads();

#pragma unroll
        for (int half = 0; half < 2; half++) {
            float S[8][4];
#pragma unroll
            for (int nt = 0; nt < 8; nt++)
#pragma unroll
                for (int e = 0; e < 4; e++) S[nt][e] = 0.0f;

#pragma unroll
            for (int ks = 0; ks < 4; ks++) {
                const int k0 = ks * 16;
                u32 aH[4], aL[4];
                {
                    u32 off = ((w * 16 + (lane & 15)) * ATT_ST + k0 + (lane >> 4) * 8) * 2;
                    ldsm_x4(aH, sb + QH_OFF + off);
                    ldsm_x4(aL, sb + QL_OFF + off);
                }
#pragma unroll
                for (int ng2 = 0; ng2 < 4; ng2++) {
                    const int ng = half * 4 + ng2;
                    u32 bH[4], bL[4];
                    u32 off = ((ng * 16 + brow_off) * ATT_ST + k0 + bcol_off) * 2;
                    ldsm_x4(bH, sb + KH_OFF + off);
                    ldsm_x4(bL, sb + KL_OFF + off);
                    mma_bf16(S[2 * ng2],     aH, bH);
                    mma_bf16(S[2 * ng2],     aH, bL);
                    mma_bf16(S[2 * ng2],     aL, bH);
                    mma_bf16(S[2 * ng2 + 1], aH, bH + 2);
                    mma_bf16(S[2 * ng2 + 1], aH, bL + 2);
                    mma_bf16(S[2 * ng2 + 1], aL, bH + 2);
                }
            }

#pragma unroll
            for (int nt = 0; nt < 8; nt++) {
                int n = (half * 8 + nt) * 8 + (lane & 3) * 2;
                float v0 = vsh[n], v1 = vsh[n + 1];
                float e0 = __expf(S[nt][0] * scale);
                float e1 = __expf(S[nt][1] * scale);
                float e2 = __expf(S[nt][2] * scale);
                float e3 = __expf(S[nt][3] * scale);
                accA[0] += e0 * v0 + e1 * v1;
                accL[0] += e0 + e1;
                accA[1] += e2 * v0 + e3 * v1;
                accL[1] += e2 + e3;
            }
        }
    }

#pragma unroll
    for (int r = 0; r < 2; r++) {
#pragma unroll
        for (int o = 1; o <= 2; o <<= 1) {
            accA[r] += __shfl_xor_sync(0xffffffffu, accA[r], o);
            accL[r] += __shfl_xor_sync(0xffffffffu, accL[r], o);
        }
    }
    if ((lane & 3) == 0) {
        int row = q0 + w * 16 + (lane >> 2);
        g_attn[((size_t)b * LQ_ + row) * HEADS + h]     = accA[0] / accL[0];
        g_attn[((size_t)b * LQ_ + row + 8) * HEADS + h] = accA[1] / accL[1];
    }
}

// ---------------- tiny MLP ----------------
__global__ __launch_bounds__(256) void mlp_kernel(
    const float* __restrict__ W1, const float* __restrict__ b1,
    const float* __restrict__ W2, const float* __restrict__ b2,
    float* __restrict__ out)
{
    int idx = blockIdx.x * blockDim.x + threadIdx.x;
    if (idx >= B_ * LQ_) return;

    float o[HEADS];
#pragma unroll
    for (int i = 0; i < HEADS; i++) o[i] = g_attn[(size_t)idx * HEADS + i];

    float y = b2[0];
#pragma unroll
    for (int j = 0; j < 10; j++) {
        float hj = b1[j];
#pragma unroll
        for (int i = 0; i < HEADS; i++) hj += o[i] * W1[i * 10 + j];
        hj = fmaxf(hj, 0.0f);
        y += hj * W2[j];
    }
    out[idx] = fmaxf(y, 0.0f);
}

// ---------------------------------------------------------------------------
extern "C" void kernel_launch(void* const* d_in, const int* in_sizes, int n_in,
                              void* d_out, int out_size)
{
    const float* query = (const float*)d_in[0];
    const float* key   = (const float*)d_in[1];
    const float* value = (const float*)d_in[2];
    const float* Wq    = (const float*)d_in[3];
    const float* bq    = (const float*)d_in[4];
    const float* Wk    = (const float*)d_in[5];
    const float* bk    = (const float*)d_in[6];
    const float* W1    = (const float*)d_in[7];
    const float* b1    = (const float*)d_in[8];
    const float* W2    = (const float*)d_in[9];
    const float* b2    = (const float*)d_in[10];
    float* out = (float*)d_out;

    // one-time host-side handles (no device memory involved; captured work
    // is identical on every call)
    static cudaStream_t sQ = nullptr;
    static cudaEvent_t evFork = nullptr, evJoin = nullptr;
    if (sQ == nullptr) {
        cudaStreamCreateWithFlags(&sQ, cudaStreamNonBlocking);
        cudaEventCreateWithFlags(&evFork, cudaEventDisableTiming);
        cudaEventCreateWithFlags(&evJoin, cudaEventDisableTiming);
    }

    __nv_bfloat16 *qh, *ql, *kh, *kl, *wqh, *wql, *wkh, *wkl;
    __nv_bfloat16 *qah, *qal, *kah, *kal;
    cudaGetSymbolAddress((void**)&qh,  g_qh);
    cudaGetSymbolAddress((void**)&ql,  g_ql);
    cudaGetSymbolAddress((void**)&kh,  g_kh);
    cudaGetSymbolAddress((void**)&kl,  g_kl);
    cudaGetSymbolAddress((void**)&wqh, g_wqh);
    cudaGetSymbolAddress((void**)&wql, g_wql);
    cudaGetSymbolAddress((void**)&wkh, g_wkh);
    cudaGetSymbolAddress((void**)&wkl, g_wkl);
    cudaGetSymbolAddress((void**)&qah, g_qah);
    cudaGetSymbolAddress((void**)&qal, g_qal);
    cudaGetSymbolAddress((void**)&kah, g_kah);
    cudaGetSymbolAddress((void**)&kal, g_kal);

    cudaFuncSetAttribute(gemm_bf16x3,
                         cudaFuncAttributeMaxDynamicSharedMemorySize, GEMM_SMEM);
    cudaFuncSetAttribute(attn_tc,
                         cudaFuncAttributeMaxDynamicSharedMemorySize, ATT_SMEM);

    // ---- fork: q-chain runs on sQ, k-chain on the default stream ----
    cudaEventRecord(evFork, 0);
    cudaStreamWaitEvent(sQ, evFork, 0);

    // q-chain (stream sQ): q split, Wq split, q projection
    split_bf16_v<<<B_ * LQ_, 256, 0, sQ>>>(query, qh, ql, B_ * LQ_, QIN, KPQ);
    split_bf16_v<<<KPQ, 64, 0, sQ>>>(Wq, wqh, wql, QIN, PROJ_, NP);
    {
        dim3 grid(NP / BN, (B_ * LQ_) / BM);
        gemm_bf16x3<<<grid, 256, GEMM_SMEM, sQ>>>(qh, ql, wqh, wql, bq,
                                                  qah, qal, KPQ, 11);
    }
    cudaEventRecord(evJoin, sQ);

    // k-chain (default stream): key split, Wk split, k projection
    split_bf16_v<<<B_ * LK_, 256>>>(key, kh, kl, B_ * LK_, KIN, KPK);
    split_bf16_v<<<KPK, 64>>>(Wk, wkh, wkl, KIN, PROJ_, NP);
    {
        dim3 grid(NP / BN, (B_ * LK_) / BM);
        gemm_bf16x3<<<grid, 256, GEMM_SMEM>>>(kh, kl, wkh, wkl, bk,
                                              kah, kal, KPK, 10);
    }

    // ---- join: attention needs both projections ----
    cudaStreamWaitEvent(0, evJoin, 0);

    {
        dim3 grid(LQ_ / 128, HEADS, B_);
        attn_tc<<<grid, 256, ATT_SMEM>>>(value);
    }
    {
        int n = B_ * LQ_;
        mlp_kernel<<<(n + 255) / 256, 256>>>(W1, b1, W2, b2, out);
    }
}

// round 11
// speedup vs baseline: 3.9737x; 1.0173x over previous
#include <cuda_runtime.h>
#include <cuda_bf16.h>
#include <math.h>

#define B_    8
#define LQ_   2048
#define LK_   1024
#define QIN   1124
#define KIN   10100
#define PROJ_ 500
#define HEADS 10
#define HD    50

#define KPQ   1152   // QIN padded
#define KPK   10112  // KIN padded
#define NP    512    // PROJ padded
#define HDP   64     // head_dim padded for MMA

typedef unsigned int u32;

// ---------------- scratch (allocation-free; zero-initialized) ----------------
__device__ float g_attn[B_ * LQ_ * HEADS];

__device__ __nv_bfloat16 g_qh[B_ * LQ_ * KPQ];   // split inputs
__device__ __nv_bfloat16 g_ql[B_ * LQ_ * KPQ];
__device__ __nv_bfloat16 g_kh[B_ * LK_ * KPK];
__device__ __nv_bfloat16 g_kl[B_ * LK_ * KPK];
__device__ __nv_bfloat16 g_wqh[KPQ * NP];        // W [Kp][NP] row-major
__device__ __nv_bfloat16 g_wql[KPQ * NP];
__device__ __nv_bfloat16 g_wkh[KPK * NP];
__device__ __nv_bfloat16 g_wkl[KPK * NP];

// projected q/k in attention layout [b, head, seq, HDP], bf16 hi/lo
__device__ __nv_bfloat16 g_qah[B_ * HEADS * LQ_ * HDP];
__device__ __nv_bfloat16 g_qal[B_ * HEADS * LQ_ * HDP];
__device__ __nv_bfloat16 g_kah[B_ * HEADS * LK_ * HDP];
__device__ __nv_bfloat16 g_kal[B_ * HEADS * LK_ * HDP];

// ------- fp32 -> (hi,lo) bf16 split, vectorized: 8 cols/thread --------------
__device__ __forceinline__ u32 pack_bf2(__nv_bfloat16 lo, __nv_bfloat16 hi) {
    return (u32)__bfloat16_as_ushort(lo) | ((u32)__bfloat16_as_ushort(hi) << 16);
}
__global__ void split_bf16_v(const float* __restrict__ X,
                             __nv_bfloat16* __restrict__ H,
                             __nv_bfloat16* __restrict__ L,
                             int rows, int cols, int colsp)
{
    int r = blockIdx.x;
    bool rv = (r < rows);
    const float* Xr = X + (size_t)r * cols;
    for (int c8 = threadIdx.x * 8; c8 < colsp; c8 += blockDim.x * 8) {
        float x[8];
        if (rv && c8 + 8 <= cols) {
            float4 a = *(const float4*)(Xr + c8);
            float4 b = *(const float4*)(Xr + c8 + 4);
            x[0] = a.x; x[1] = a.y; x[2] = a.z; x[3] = a.w;
            x[4] = b.x; x[5] = b.y; x[6] = b.z; x[7] = b.w;
        } else {
#pragma unroll
            for (int i = 0; i < 8; i++) {
                int c = c8 + i;
                x[i] = (rv && c < cols) ? Xr[c] : 0.0f;
            }
        }
        __nv_bfloat16 hb[8], lb[8];
#pragma unroll
        for (int i = 0; i < 8; i++) {
            hb[i] = __float2bfloat16(x[i]);
            lb[i] = __float2bfloat16(x[i] - __bfloat162float(hb[i]));
        }
        size_t o = (size_t)r * colsp + c8;
        uint4 hv, lv;
        hv.x = pack_bf2(hb[0], hb[1]); hv.y = pack_bf2(hb[2], hb[3]);
        hv.z = pack_bf2(hb[4], hb[5]); hv.w = pack_bf2(hb[6], hb[7]);
        lv.x = pack_bf2(lb[0], lb[1]); lv.y = pack_bf2(lb[2], lb[3]);
        lv.z = pack_bf2(lb[4], lb[5]); lv.w = pack_bf2(lb[6], lb[7]);
        *(uint4*)(H + o) = hv;
        *(uint4*)(L + o) = lv;
    }
}

// ---------------- mma / ldmatrix / cp.async helpers ----------------
__device__ __forceinline__ void ldsm_x4(u32* r, u32 addr) {
    asm volatile("ldmatrix.sync.aligned.m8n8.x4.shared.b16 {%0,%1,%2,%3}, [%4];"
        : "=r"(r[0]), "=r"(r[1]), "=r"(r[2]), "=r"(r[3]) : "r"(addr));
}
__device__ __forceinline__ void ldsm_x4_t(u32* r, u32 addr) {
    asm volatile("ldmatrix.sync.aligned.m8n8.x4.trans.shared.b16 {%0,%1,%2,%3}, [%4];"
        : "=r"(r[0]), "=r"(r[1]), "=r"(r[2]), "=r"(r[3]) : "r"(addr));
}
__device__ __forceinline__ void mma_bf16(float* d, const u32* a, const u32* b) {
    asm volatile(
        "mma.sync.aligned.m16n8k16.row.col.f32.bf16.bf16.f32 "
        "{%0,%1,%2,%3},{%4,%5,%6,%7},{%8,%9},{%0,%1,%2,%3};"
        : "+f"(d[0]), "+f"(d[1]), "+f"(d[2]), "+f"(d[3])
        : "r"(a[0]), "r"(a[1]), "r"(a[2]), "r"(a[3]), "r"(b[0]), "r"(b[1]));
}
__device__ __forceinline__ void cp16(u32 dst, const void* src) {
    asm volatile("cp.async.cg.shared.global [%0], [%1], 16;"
                 :: "r"(dst), "l"(src));
}
__device__ __forceinline__ void cp_commit() {
    asm volatile("cp.async.commit_group;" ::: "memory");
}
template <int N>
__device__ __forceinline__ void cp_wait() {
    asm volatile("cp.async.wait_group %0;" :: "n"(N) : "memory");
}

// ------- bf16x3 GEMM: cp.async pipeline, 128x128 CTA tile, pass-major MMAs --
#define BM  128
#define BN  128
#define BKB 32
#define AST 40
#define WST 136
#define A_BUF (BM * AST)
#define W_BUF (BKB * WST)
#define GEMM_SMEM ((4 * A_BUF + 4 * W_BUF) * 2)   // 75776 B

__global__ __launch_bounds__(256, 2) void gemm_bf16x3(
    const __nv_bfloat16* __restrict__ Ah, const __nv_bfloat16* __restrict__ Al,
    const __nv_bfloat16* __restrict__ Wh, const __nv_bfloat16* __restrict__ Wl,
    const float* __restrict__ bias,
    __nv_bfloat16* __restrict__ DH, __nv_bfloat16* __restrict__ DL,
    int Kp, int seqshift)
{
    extern __shared__ __nv_bfloat16 sm[];
    __nv_bfloat16* sAh = sm;
    __nv_bfloat16* sAl = sm + 2 * A_BUF;
    __nv_bfloat16* sWh = sm + 4 * A_BUF;
    __nv_bfloat16* sWl = sm + 4 * A_BUF + 2 * W_BUF;
    const u32 bAh0 = (u32)__cvta_generic_to_shared(sAh);
    const u32 bAl0 = (u32)__cvta_generic_to_shared(sAl);
    const u32 bWh0 = (u32)__cvta_generic_to_shared(sWh);
    const u32 bWl0 = (u32)__cvta_generic_to_shared(sWl);

    const int t    = threadIdx.x;
    const int lane = t & 31;
    const int warp = t >> 5;
    const int wm   = warp >> 1;
    const int wn   = warp & 1;
    const int m0   = blockIdx.y * BM;
    const int n0   = blockIdx.x * BN;

    const int ar = t >> 1;
    const int ac = (t & 1) * 2;
    const int wr = t >> 3;
    const int wc = t & 7;

    auto load_tile = [&](int buf, int k0) {
#pragma unroll
        for (int i = 0; i < 2; i++) {
            int ch = ac + i;
            size_t g = (size_t)(m0 + ar) * Kp + k0 + ch * 8;
            u32 s = (u32)((buf * A_BUF + ar * AST + ch * 8) * 2);
            cp16(bAh0 + s, Ah + g);
            cp16(bAl0 + s, Al + g);
        }
#pragma unroll
        for (int i = 0; i < 2; i++) {
            int ch = wc + i * 8;
            size_t g = (size_t)(k0 + wr) * NP + n0 + ch * 8;
            u32 s = (u32)((buf * W_BUF + wr * WST + ch * 8) * 2);
            cp16(bWh0 + s, Wh + g);
            cp16(bWl0 + s, Wl + g);
        }
        cp_commit();
    };

    float acc[2][8][4];
#pragma unroll
    for (int mt = 0; mt < 2; mt++)
#pragma unroll
        for (int nt = 0; nt < 8; nt++)
#pragma unroll
            for (int e = 0; e < 4; e++) acc[mt][nt][e] = 0.0f;

    const int lrow = lane & 15;
    const int lcol = lane >> 4;
    const int ntiles = Kp / BKB;

    load_tile(0, 0);
    if (ntiles > 1) load_tile(1, BKB);

    for (int tl = 0; tl < ntiles; ++tl) {
        const int cur = tl & 1;
        if (tl + 1 < ntiles) cp_wait<1>(); else cp_wait<0>();
        __syncthreads();

        const u32 aHb = bAh0 + cur * A_BUF * 2;
        const u32 aLb = bAl0 + cur * A_BUF * 2;
        const u32 wHb = bWh0 + cur * W_BUF * 2;
        const u32 wLb = bWl0 + cur * W_BUF * 2;

#pragma unroll
        for (int kk = 0; kk < 2; kk++) {
            u32 aH[2][4], aL[2][4];
#pragma unroll
            for (int mt = 0; mt < 2; mt++) {
                u32 off = ((wm * 32 + mt * 16 + lrow) * AST + kk * 16 + lcol * 8) * 2;
                ldsm_x4(aH[mt], aHb + off);
                ldsm_x4(aL[mt], aLb + off);
            }
            // nq processed in pairs; within a pair, MMAs are PASS-MAJOR so each
            // accumulator is revisited at distance 8 (breaks RAW chains)
#pragma unroll
            for (int np2 = 0; np2 < 2; np2++) {
                u32 bH[2][4], bL[2][4];
#pragma unroll
                for (int q = 0; q < 2; q++) {
                    int nq = np2 * 2 + q;
                    u32 off = ((kk * 16 + lrow) * WST + wn * 64 + nq * 16 + lcol * 8) * 2;
                    ldsm_x4_t(bH[q], wHb + off);
                    ldsm_x4_t(bL[q], wLb + off);
                }
                // pass 1: aH x bH
#pragma unroll
                for (int mt = 0; mt < 2; mt++)
#pragma unroll
                    for (int q = 0; q < 2; q++)
#pragma unroll
                        for (int j = 0; j < 2; j++)
                            mma_bf16(acc[mt][(np2 * 2 + q) * 2 + j], aH[mt], bH[q] + 2 * j);
                // pass 2: aH x bL
#pragma unroll
                for (int mt = 0; mt < 2; mt++)
#pragma unroll
                    for (int q = 0; q < 2; q++)
#pragma unroll
                        for (int j = 0; j < 2; j++)
                            mma_bf16(acc[mt][(np2 * 2 + q) * 2 + j], aH[mt], bL[q] + 2 * j);
                // pass 3: aL x bH
#pragma unroll
                for (int mt = 0; mt < 2; mt++)
#pragma unroll
                    for (int q = 0; q < 2; q++)
#pragma unroll
                        for (int j = 0; j < 2; j++)
                            mma_bf16(acc[mt][(np2 * 2 + q) * 2 + j], aL[mt], bH[q] + 2 * j);
            }
        }

        __syncthreads();
        if (tl + 2 < ntiles) load_tile(cur, (tl + 2) * BKB);
    }

    const int seqlen = 1 << seqshift;
#pragma unroll
    for (int mt = 0; mt < 2; mt++) {
#pragma unroll
        for (int nt = 0; nt < 8; nt++) {
            int row = wm * 32 + mt * 16 + (lane >> 2);
            int col = wn * 64 + nt * 8 + (lane & 3) * 2;
#pragma unroll
            for (int e = 0; e < 4; e++) {
                int m = m0 + row + ((e >> 1) ? 8 : 0);
                int n = n0 + col + (e & 1);
                if (n >= PROJ_) continue;
                int head = n / HD;
                int c    = n - head * HD;
                int bi   = m >> seqshift;
                int si   = m & (seqlen - 1);
                float x = acc[mt][nt][e] + bias[n];
                __nv_bfloat16 h = __float2bfloat16(x);
                size_t o = ((size_t)(bi * HEADS + head) * seqlen + si) * HDP + c;
                DH[o] = h;
                DL[o] = __float2bfloat16(x - __bfloat162float(h));
            }
        }
    }
}

// ---------------- tensor-core attention (pass-major MMA order) --------------
#define ATT_ST 72
#define QH_OFF 0
#define QL_OFF (128 * ATT_ST * 2)
#define KH_OFF (2 * QL_OFF)
#define KL_OFF (3 * QL_OFF)
#define V_OFF  (4 * QL_OFF)
#define ATT_SMEM (V_OFF + 128 * 4)

__global__ __launch_bounds__(256, 2) void attn_tc(const float* __restrict__ value)
{
    extern __shared__ char smc[];
    const u32 sb = (u32)__cvta_generic_to_shared(smc);
    float* vsh = (float*)(smc + V_OFF);

    const int b  = blockIdx.z;
    const int h  = blockIdx.y;
    const int q0 = blockIdx.x * 128;
    const int t  = threadIdx.x;
    const int lane = t & 31;
    const int w    = t >> 5;

    {
        const __nv_bfloat16* qh = g_qah + ((size_t)(b * HEADS + h) * LQ_ + q0) * HDP;
        const __nv_bfloat16* ql = g_qal + ((size_t)(b * HEADS + h) * LQ_ + q0) * HDP;
#pragma unroll
        for (int i = 0; i < 4; i++) {
            int idx = t + i * 256;
            int r = idx >> 3, c = idx & 7;
            uint4 vh = *(const uint4*)(qh + (size_t)r * HDP + c * 8);
            uint4 vl = *(const uint4*)(ql + (size_t)r * HDP + c * 8);
            *(uint4*)(smc + QH_OFF + (r * ATT_ST + c * 8) * 2) = vh;
            *(uint4*)(smc + QL_OFF + (r * ATT_ST + c * 8) * 2) = vl;
        }
    }

    float accA[2] = {0.f, 0.f}, accL[2] = {0.f, 0.f};
    const float scale = 0.14142135623730951f;

    const int bg  = lane >> 3;
    const int bi8 = lane & 7;
    const int brow_off = ((bg & 2) ? 8 : 0) + bi8;
    const int bcol_off = (bg & 1) ? 8 : 0;

    for (int kt = 0; kt < LK_; kt += 128) {
        __syncthreads();
        {
            const __nv_bfloat16* kh = g_kah + ((size_t)(b * HEADS + h) * LK_ + kt) * HDP;
            const __nv_bfloat16* kl = g_kal + ((size_t)(b * HEADS + h) * LK_ + kt) * HDP;
#pragma unroll
            for (int i = 0; i < 4; i++) {
                int idx = t + i * 256;
                int r = idx >> 3, c = idx & 7;
                uint4 vh = *(const uint4*)(kh + (size_t)r * HDP + c * 8);
                uint4 vl = *(const uint4*)(kl + (size_t)r * HDP + c * 8);
                *(uint4*)(smc + KH_OFF + (r * ATT_ST + c * 8) * 2) = vh;
                *(uint4*)(smc + KL_OFF + (r * ATT_ST + c * 8) * 2) = vl;
            }
            if (t < 128) vsh[t] = value[b * LK_ + kt + t];
        }
        __syncthreads();

#pragma unroll
        for (int half = 0; half < 2; half++) {
            float S[8][4];
#pragma unroll
            for (int nt = 0; nt < 8; nt++)
#pragma unroll
                for (int e = 0; e < 4; e++) S[nt][e] = 0.0f;

#pragma unroll
            for (int ks = 0; ks < 4; ks++) {
                const int k0 = ks * 16;
                u32 aH[4], aL[4];
                {
                    u32 off = ((w * 16 + (lane & 15)) * ATT_ST + k0 + (lane >> 4) * 8) * 2;
                    ldsm_x4(aH, sb + QH_OFF + off);
                    ldsm_x4(aL, sb + QL_OFF + off);
                }
                u32 bH[4][4], bL[4][4];
#pragma unroll
                for (int ng2 = 0; ng2 < 4; ng2++) {
                    const int ng = half * 4 + ng2;
                    u32 off = ((ng * 16 + brow_off) * ATT_ST + k0 + bcol_off) * 2;
                    ldsm_x4(bH[ng2], sb + KH_OFF + off);
                    ldsm_x4(bL[ng2], sb + KL_OFF + off);
                }
                // pass-major: each S acc revisited at distance 8
#pragma unroll
                for (int ng2 = 0; ng2 < 4; ng2++)
#pragma unroll
                    for (int j = 0; j < 2; j++)
                        mma_bf16(S[2 * ng2 + j], aH, bH[ng2] + 2 * j);
#pragma unroll
                for (int ng2 = 0; ng2 < 4; ng2++)
#pragma unroll
                    for (int j = 0; j < 2; j++)
                        mma_bf16(S[2 * ng2 + j], aH, bL[ng2] + 2 * j);
#pragma unroll
                for (int ng2 = 0; ng2 < 4; ng2++)
#pragma unroll
                    for (int j = 0; j < 2; j++)
                        mma_bf16(S[2 * ng2 + j], aL, bH[ng2] + 2 * j);
            }

#pragma unroll
            for (int nt = 0; nt < 8; nt++) {
                int n = (half * 8 + nt) * 8 + (lane & 3) * 2;
                float v0 = vsh[n], v1 = vsh[n + 1];
                float e0 = __expf(S[nt][0] * scale);
                float e1 = __expf(S[nt][1] * scale);
                float e2 = __expf(S[nt][2] * scale);
                float e3 = __expf(S[nt][3] * scale);
                accA[0] += e0 * v0 + e1 * v1;
                accL[0] += e0 + e1;
                accA[1] += e2 * v0 + e3 * v1;
                accL[1] += e2 + e3;
            }
        }
    }

#pragma unroll
    for (int r = 0; r < 2; r++) {
#pragma unroll
        for (int o = 1; o <= 2; o <<= 1) {
            accA[r] += __shfl_xor_sync(0xffffffffu, accA[r], o);
            accL[r] += __shfl_xor_sync(0xffffffffu, accL[r], o);
        }
    }
    if ((lane & 3) == 0) {
        int row = q0 + w * 16 + (lane >> 2);
        g_attn[((size_t)b * LQ_ + row) * HEADS + h]     = accA[0] / accL[0];
        g_attn[((size_t)b * LQ_ + row + 8) * HEADS + h] = accA[1] / accL[1];
    }
}

// ---------------- tiny MLP ----------------
__global__ __launch_bounds__(256) void mlp_kernel(
    const float* __restrict__ W1, const float* __restrict__ b1,
    const float* __restrict__ W2, const float* __restrict__ b2,
    float* __restrict__ out)
{
    int idx = blockIdx.x * blockDim.x + threadIdx.x;
    if (idx >= B_ * LQ_) return;

    float o[HEADS];
#pragma unroll
    for (int i = 0; i < HEADS; i++) o[i] = g_attn[(size_t)idx * HEADS + i];

    float y = b2[0];
#pragma unroll
    for (int j = 0; j < 10; j++) {
        float hj = b1[j];
#pragma unroll
        for (int i = 0; i < HEADS; i++) hj += o[i] * W1[i * 10 + j];
        hj = fmaxf(hj, 0.0f);
        y += hj * W2[j];
    }
    out[idx] = fmaxf(y, 0.0f);
}

// ---------------------------------------------------------------------------
extern "C" void kernel_launch(void* const* d_in, const int* in_sizes, int n_in,
                              void* d_out, int out_size)
{
    const float* query = (const float*)d_in[0];
    const float* key   = (const float*)d_in[1];
    const float* value = (const float*)d_in[2];
    const float* Wq    = (const float*)d_in[3];
    const float* bq    = (const float*)d_in[4];
    const float* Wk    = (const float*)d_in[5];
    const float* bk    = (const float*)d_in[6];
    const float* W1    = (const float*)d_in[7];
    const float* b1    = (const float*)d_in[8];
    const float* W2    = (const float*)d_in[9];
    const float* b2    = (const float*)d_in[10];
    float* out = (float*)d_out;

    static cudaStream_t sQ = nullptr;
    static cudaEvent_t evFork = nullptr, evJoin = nullptr;
    if (sQ == nullptr) {
        cudaStreamCreateWithFlags(&sQ, cudaStreamNonBlocking);
        cudaEventCreateWithFlags(&evFork, cudaEventDisableTiming);
        cudaEventCreateWithFlags(&evJoin, cudaEventDisableTiming);
    }

    __nv_bfloat16 *qh, *ql, *kh, *kl, *wqh, *wql, *wkh, *wkl;
    __nv_bfloat16 *qah, *qal, *kah, *kal;
    cudaGetSymbolAddress((void**)&qh,  g_qh);
    cudaGetSymbolAddress((void**)&ql,  g_ql);
    cudaGetSymbolAddress((void**)&kh,  g_kh);
    cudaGetSymbolAddress((void**)&kl,  g_kl);
    cudaGetSymbolAddress((void**)&wqh, g_wqh);
    cudaGetSymbolAddress((void**)&wql, g_wql);
    cudaGetSymbolAddress((void**)&wkh, g_wkh);
    cudaGetSymbolAddress((void**)&wkl, g_wkl);
    cudaGetSymbolAddress((void**)&qah, g_qah);
    cudaGetSymbolAddress((void**)&qal, g_qal);
    cudaGetSymbolAddress((void**)&kah, g_kah);
    cudaGetSymbolAddress((void**)&kal, g_kal);

    cudaFuncSetAttribute(gemm_bf16x3,
                         cudaFuncAttributeMaxDynamicSharedMemorySize, GEMM_SMEM);
    cudaFuncSetAttribute(attn_tc,
                         cudaFuncAttributeMaxDynamicSharedMemorySize, ATT_SMEM);

    // ---- fork: q-chain runs on sQ, k-chain on the default stream ----
    cudaEventRecord(evFork, 0);
    cudaStreamWaitEvent(sQ, evFork, 0);

    // q-chain (stream sQ)
    split_bf16_v<<<B_ * LQ_, 256, 0, sQ>>>(query, qh, ql, B_ * LQ_, QIN, KPQ);
    split_bf16_v<<<KPQ, 64, 0, sQ>>>(Wq, wqh, wql, QIN, PROJ_, NP);
    {
        dim3 grid(NP / BN, (B_ * LQ_) / BM);
        gemm_bf16x3<<<grid, 256, GEMM_SMEM, sQ>>>(qh, ql, wqh, wql, bq,
                                                  qah, qal, KPQ, 11);
    }
    cudaEventRecord(evJoin, sQ);

    // k-chain (default stream)
    split_bf16_v<<<B_ * LK_, 256>>>(key, kh, kl, B_ * LK_, KIN, KPK);
    split_bf16_v<<<KPK, 64>>>(Wk, wkh, wkl, KIN, PROJ_, NP);
    {
        dim3 grid(NP / BN, (B_ * LK_) / BM);
        gemm_bf16x3<<<grid, 256, GEMM_SMEM>>>(kh, kl, wkh, wkl, bk,
                                              kah, kal, KPK, 10);
    }

    // ---- join ----
    cudaStreamWaitEvent(0, evJoin, 0);

    {
        dim3 grid(LQ_ / 128, HEADS, B_);
        attn_tc<<<grid, 256, ATT_SMEM>>>(value);
    }
    {
        int n = B_ * LQ_;
        mlp_kernel<<<(n + 255) / 256, 256>>>(W1, b1, W2, b2, out);
    }
}